// round 13
// baseline (speedup 1.0000x reference)
#include <cuda_runtime.h>
#include <cstdint>

#define NTOK   49
#define DIM    128
#define NWIN   4096
#define SCALE  0.17677669529663687f

// ---- global scratch (static __device__, no allocation) ----
__device__ float g_wq[49152];                      // w_qkv, tf32 B-frag-packed (lane-ordered)
__device__ float g_wp[16384];                      // w_proj, tf32 B-frag-packed
__device__ float g_qkv[77070336];                  // [200704][384]  Q(scaled)|K|V raw
__device__ float g_ao[25690112];                   // [200704][128]  attention output raw
__device__ __align__(16) uint16_t g_bm[652288];    // [64][4][49][52] bf16 bias+mask

__device__ __forceinline__ uint32_t f2tf(float f) {
    uint32_t u;
    asm("cvt.rna.tf32.f32 %0, %1;" : "=r"(u) : "f"(f));
    return u;
}
__device__ __forceinline__ void mma8(float* c, const uint32_t* a, uint32_t b0, uint32_t b1) {
    asm("mma.sync.aligned.m16n8k8.row.col.f32.tf32.tf32.f32 "
        "{%0,%1,%2,%3},{%4,%5,%6,%7},{%8,%9},{%0,%1,%2,%3};"
        : "+f"(c[0]), "+f"(c[1]), "+f"(c[2]), "+f"(c[3])
        : "r"(a[0]), "r"(a[1]), "r"(a[2]), "r"(a[3]), "r"(b0), "r"(b1));
}
__device__ __forceinline__ void cpa16(uint32_t s, const void* g) {
    asm volatile("cp.async.cg.shared.global [%0], [%1], 16;" :: "r"(s), "l"(g));
}
__device__ __forceinline__ uint32_t smem_u32(const void* p) {
    uint32_t a;
    asm("{ .reg .u64 t; cvta.to.shared.u64 t, %1; cvt.u32.u64 %0, t; }" : "=r"(a) : "l"(p));
    return a;
}
__device__ __forceinline__ uint16_t f2bf(float f) {
    uint32_t u = __float_as_uint(f);
    return (uint16_t)((u + 0x7fffu + ((u >> 16) & 1u)) >> 16);
}

// ---- prep: pack weights into tf32 B-fragment order (lane-ordered) ----
__global__ void prep_kernel(const float* __restrict__ wq, const float* __restrict__ wp) {
    int o = blockIdx.x * blockDim.x + threadIdx.x;        // 65536 total
    int oo = (o < 49152) ? o : o - 49152;
    int slot = oo & 3;
    int lane = (oo >> 2) & 31;
    int kt   = (oo >> 7) & 15;
    int nt   = oo >> 11;
    int tig = lane & 3, gid = lane >> 2;
    int k = kt * 8 + tig + 4 * (slot & 1);
    int n = nt * 16 + gid + 8 * (slot >> 1);
    if (o < 49152) g_wq[oo] = __uint_as_float(f2tf(wq[k * 384 + n]));
    else           g_wp[oo] = __uint_as_float(f2tf(wp[k * 128 + n]));
}

// ---- prep_bm: bm[w][h][r][c52] = btab[ri[r,c],h] + mask[w,r,c]  (bf16) ----
__global__ void prep_bm(const float* __restrict__ mask, const float* __restrict__ btab,
                        const int* __restrict__ relidx) {
    int o = blockIdx.x * blockDim.x + threadIdx.x;        // 652288 total
    if (o >= 652288) return;
    int c = o % 52;
    int t = o / 52;
    int r = t % 49; t /= 49;
    int h = t & 3;
    int w = t >> 2;
    float v = 0.f;
    if (c < 49)
        v = btab[relidx[r * 49 + c] * 4 + h] + mask[w * 2401 + r * 49 + c];
    g_bm[o] = f2bf(v);
}

// ============================================================
// GEMM: C[64 x NO] = A * B_packed + bias, K=128, NS slices of 128
// ============================================================
#define GA_LD 132
#define GS_B  8448
#define GS_BS 24832
#define GEMM_SMEMF 25216           // 100864 B -> 2 blocks/SM

template<int MODE>
__global__ void __launch_bounds__(256, 2)
gemm_k128(const float* __restrict__ Aext, const float* __restrict__ bias,
          float* __restrict__ Cext)
{
    extern __shared__ float sm[];
    float* bs = sm + GS_BS;
    const int tid = threadIdx.x, wid = tid >> 5, lane = tid & 31;
    const int gid = lane >> 2, tig = lane & 3;
    const uint32_t su = smem_u32(sm);

    const float* A  = (MODE == 0) ? Aext : g_ao;
    const float* Bp = (MODE == 0) ? g_wq : g_wp;
    const int    NO = (MODE == 0) ? 384 : 128;
    const int    NS = (MODE == 0) ? 3 : 1;
    float*       C  = (MODE == 0) ? g_qkv : Cext;

    const size_t arow0 = (size_t)blockIdx.x * 64;
    for (int i = tid; i < 2048; i += 256) {               // raw A 64x128
        int r = i >> 5, c4 = i & 31;
        cpa16(su + (r * GA_LD + c4 * 4) * 4, A + (arow0 + r) * DIM + c4 * 4);
    }
    for (int i = tid; i < NO / 4; i += 256)               // bias
        cpa16(su + (GS_BS + i * 4) * 4, bias + i * 4);
    asm volatile("cp.async.commit_group;");
    for (int i = tid; i < 4096; i += 256)                 // B slice 0
        cpa16(su + (GS_B + i * 4) * 4, Bp + i * 4);
    asm volatile("cp.async.commit_group;");
    asm volatile("cp.async.wait_group 1;");
    __syncthreads();

    // ---- one-time in-smem A repack, lane-ordered ----
    float4 stg[8];
#pragma unroll
    for (int j = 0; j < 8; j++) {
        const int u = tid + 256 * j;
        const int mt = u >> 9, kt = (u >> 5) & 15;
        const int l = u & 31, gd = (l >> 2) & 7, tg = l & 3;
        const int r = mt * 16 + gd, c = kt * 8 + tg;
        stg[j].x = __uint_as_float(f2tf(sm[r * GA_LD + c]));
        stg[j].y = __uint_as_float(f2tf(sm[(r + 8) * GA_LD + c]));
        stg[j].z = __uint_as_float(f2tf(sm[r * GA_LD + c + 4]));
        stg[j].w = __uint_as_float(f2tf(sm[(r + 8) * GA_LD + c + 4]));
    }
    __syncthreads();
    {
        float4* As4w = (float4*)sm;
#pragma unroll
        for (int j = 0; j < 8; j++) As4w[tid + 256 * j] = stg[j];
    }
    asm volatile("cp.async.wait_group 0;");
    __syncthreads();

    const int mw = wid & 1, nw = wid >> 1;
    const uint4* As4 = (const uint4*)sm;
    const uint4* Bs4 = (const uint4*)(sm + GS_B);

#pragma unroll 1
    for (int t = 0; t < NS; t++) {
        float c[2][4][4];
#pragma unroll
        for (int f = 0; f < 2; f++)
#pragma unroll
            for (int j = 0; j < 4; j++)
#pragma unroll
                for (int e = 0; e < 4; e++) c[f][j][e] = 0.f;

#pragma unroll
        for (int kt = 0; kt < 16; kt++) {
            uint4 av0 = As4[((mw * 2 + 0) * 16 + kt) * 32 + lane];
            uint4 av1 = As4[((mw * 2 + 1) * 16 + kt) * 32 + lane];
            uint4 bv0 = Bs4[((nw * 2 + 0) * 16 + kt) * 32 + lane];
            uint4 bv1 = Bs4[((nw * 2 + 1) * 16 + kt) * 32 + lane];
            mma8(c[0][0], (const uint32_t*)&av0, bv0.x, bv0.y);
            mma8(c[0][1], (const uint32_t*)&av0, bv0.z, bv0.w);
            mma8(c[0][2], (const uint32_t*)&av0, bv1.x, bv1.y);
            mma8(c[0][3], (const uint32_t*)&av0, bv1.z, bv1.w);
            mma8(c[1][0], (const uint32_t*)&av1, bv0.x, bv0.y);
            mma8(c[1][1], (const uint32_t*)&av1, bv0.z, bv0.w);
            mma8(c[1][2], (const uint32_t*)&av1, bv1.x, bv1.y);
            mma8(c[1][3], (const uint32_t*)&av1, bv1.z, bv1.w);
        }

        __syncthreads();
        if (t + 1 < NS) {
            const float* Bn = Bp + (t + 1) * 16384;
            for (int i = tid; i < 4096; i += 256)
                cpa16(su + (GS_B + i * 4) * 4, Bn + i * 4);
            asm volatile("cp.async.commit_group;");
        }

        const int   cb = t * 128;
        const float sc = (MODE == 0 && t == 0) ? SCALE : 1.f;
#pragma unroll
        for (int f = 0; f < 2; f++) {
            const size_t r0 = arow0 + (mw * 2 + f) * 16 + gid;
#pragma unroll
            for (int j = 0; j < 4; j++) {
                const int cl = nw * 32 + j * 8 + 2 * tig;
                const float b0 = bs[cb + cl], b1 = bs[cb + cl + 1];
                const int cg = cb + cl;
                *(float2*)&C[r0 * NO + cg] =
                    make_float2((c[f][j][0] + b0) * sc, (c[f][j][1] + b1) * sc);
                *(float2*)&C[(r0 + 8) * NO + cg] =
                    make_float2((c[f][j][2] + b0) * sc, (c[f][j][3] + b1) * sc);
            }
        }
        if (t + 1 < NS) {
            asm volatile("cp.async.wait_group 0;");
            __syncthreads();
        }
    }
}

// ============================================================
// Attention: K/V repacked to lane-ordered tf32 frags in smem,
// register softmax with bf16 fused bias+mask, shfl P-permute.
// smem: Q raw 56x132 | packed KV 14336 | bm 5096
// ============================================================
#define Q_LD   132
#define AS_KV  7392
#define AS_BM  21728
#define ATTN_SMEMF 26824           // 107296 B -> 2 blocks/SM

__global__ void __launch_bounds__(256, 2)
attn_kernel(int dummy)
{
    extern __shared__ float sm[];
    float* qs = sm;
    const uint32_t* bm32 = (const uint32_t*)(sm + AS_BM);
    const int tid = threadIdx.x, wid = tid >> 5, lane = tid & 31;
    const int gid = lane >> 2, tig = lane & 3;
    const uint32_t su = smem_u32(sm);

    const int wb = blockIdx.x;
    const size_t row0 = (size_t)wb * NTOK;
    for (int i = tid; i < 1568; i += 256) {               // Q raw 49x128
        int r = i >> 5, c4 = i & 31;
        cpa16(su + (r * Q_LD + c4 * 4) * 4, g_qkv + (row0 + r) * 384 + c4 * 4);
    }
    for (int i = tid; i < 3136; i += 256) {               // KV raw 49x256, stride 260
        int r = i >> 6, c4 = i & 63;
        cpa16(su + (AS_KV + r * 260 + c4 * 4) * 4, g_qkv + (row0 + r) * 384 + 128 + c4 * 4);
    }
    const int w = wb & 63;
    {
        const char* bsrc = (const char*)g_bm + (size_t)w * 20384;
        for (int i = tid; i < 1274; i += 256)
            cpa16(su + AS_BM * 4 + i * 16, bsrc + i * 16);
    }
    for (int i = tid; i < 7 * Q_LD; i += 256) qs[49 * Q_LD + i] = 0.f;  // zero Q rows 49..55
    asm volatile("cp.async.commit_group;\n\tcp.async.wait_group 0;");
    __syncthreads();

    // ---- one-time K/V repack to lane-ordered tf32 frags (register-staged) ----
    // K uint2 idx ((h*7+nt)*4+kt)*32+l : {K[nt*8+gd][kt*8+tg], [..+4]}
    // V uint2 idx 3584+((h*4+nf)*7+kt)*32+l : {V[kt*8+tg][h32+nf*8+gd], V[kt*8+tg+4][..]}
    {
        const float* stage = sm + AS_KV;
        float2 stg[28];
#pragma unroll
        for (int j = 0; j < 28; j++) {
            const int u = tid + 256 * j;
            float a, b;
            if (u < 3584) {
                const int l = u & 31, kt = (u >> 5) & 3, t2 = u >> 7;
                const int nt = t2 % 7, h2 = t2 / 7;
                const int gd = l >> 2, tg = l & 3;
                const int row = nt * 8 + gd, col = h2 * 32 + kt * 8 + tg;
                a = (row < NTOK) ? stage[row * 260 + col] : 0.f;
                b = (row < NTOK) ? stage[row * 260 + col + 4] : 0.f;
            } else {
                const int v = u - 3584;
                const int l = v & 31, k7 = (v >> 5) % 7, t3 = (v >> 5) / 7;
                const int nf = t3 & 3, h2 = t3 >> 2;
                const int gd = l >> 2, tg = l & 3;
                const int row = k7 * 8 + tg, col = 128 + h2 * 32 + nf * 8 + gd;
                a = (row < NTOK)     ? stage[row * 260 + col]       : 0.f;
                b = (row + 4 < NTOK) ? stage[(row + 4) * 260 + col] : 0.f;
            }
            stg[j].x = __uint_as_float(f2tf(a));
            stg[j].y = __uint_as_float(f2tf(b));
        }
        __syncthreads();
        float2* kv2 = (float2*)(sm + AS_KV);
#pragma unroll
        for (int j = 0; j < 28; j++) kv2[tid + 256 * j] = stg[j];
    }
    __syncthreads();

    const uint2* kp2 = (const uint2*)(sm + AS_KV);
    const uint2* vp2 = kp2 + 3584;
    const int h = wid & 3, mt = wid >> 2;
#pragma unroll 1
    for (int sub = 0; sub < 2; sub++) {
        const int m0 = (mt * 2 + sub) * 16;
        const bool hiO = (m0 == 48);

        uint32_t aq[4][4];
#pragma unroll
        for (int kt = 0; kt < 4; kt++) {
            const float* p = qs + (m0 + gid) * Q_LD + h * 32 + kt * 8 + tig;
            aq[kt][0] = f2tf(p[0]);
            aq[kt][2] = f2tf(p[4]);
            aq[kt][1] = hiO ? 0u : f2tf(p[8 * Q_LD]);
            aq[kt][3] = hiO ? 0u : f2tf(p[8 * Q_LD + 4]);
        }
        float s_[7][4];
#pragma unroll
        for (int nt = 0; nt < 7; nt++) {
            float cc[4] = {0.f, 0.f, 0.f, 0.f};
#pragma unroll
            for (int kt = 0; kt < 4; kt++) {
                uint2 kv = kp2[((h * 7 + nt) * 4 + kt) * 32 + lane];
                mma8(cc, aq[kt], kv.x, kv.y);
            }
#pragma unroll
            for (int e = 0; e < 4; e++) s_[nt][e] = cc[e];
        }

        const int r0 = m0 + gid, r1 = r0 + 8;
        const bool v0 = r0 < NTOK, v1 = r1 < NTOK;
        const int br0 = (h * 49 + (v0 ? r0 : 0)) * 26;
        const int br1 = (h * 49 + (v1 ? r1 : 0)) * 26;
        float lo[7][2], hi[7][2];
        float mx0 = -1e30f, mx1 = -1e30f;
#pragma unroll
        for (int nt = 0; nt < 7; nt++) {
            const int cc0 = nt * 8 + 2 * tig;
            const uint32_t bv0 = bm32[br0 + nt * 4 + tig];
            const uint32_t bv1 = bm32[br1 + nt * 4 + tig];
            const float b00 = __uint_as_float(bv0 << 16);
            const float b01 = __uint_as_float(bv0 & 0xffff0000u);
            const float b10 = __uint_as_float(bv1 << 16);
            const float b11 = __uint_as_float(bv1 & 0xffff0000u);
            lo[nt][0] = (v0 && cc0     < NTOK) ? s_[nt][0] + b00 : -1e30f;
            lo[nt][1] = (v0 && cc0 + 1 < NTOK) ? s_[nt][1] + b01 : -1e30f;
            hi[nt][0] = (v1 && cc0     < NTOK) ? s_[nt][2] + b10 : -1e30f;
            hi[nt][1] = (v1 && cc0 + 1 < NTOK) ? s_[nt][3] + b11 : -1e30f;
            mx0 = fmaxf(mx0, fmaxf(lo[nt][0], lo[nt][1]));
            mx1 = fmaxf(mx1, fmaxf(hi[nt][0], hi[nt][1]));
        }
        mx0 = fmaxf(mx0, __shfl_xor_sync(0xffffffffu, mx0, 1));
        mx0 = fmaxf(mx0, __shfl_xor_sync(0xffffffffu, mx0, 2));
        mx1 = fmaxf(mx1, __shfl_xor_sync(0xffffffffu, mx1, 1));
        mx1 = fmaxf(mx1, __shfl_xor_sync(0xffffffffu, mx1, 2));
        float s0 = 0.f, s1 = 0.f;
#pragma unroll
        for (int nt = 0; nt < 7; nt++)
#pragma unroll
            for (int s = 0; s < 2; s++) {
                float e0 = __expf(lo[nt][s] - mx0);
                float e1 = __expf(hi[nt][s] - mx1);
                lo[nt][s] = e0; hi[nt][s] = e1;
                s0 += e0; s1 += e1;
            }
        s0 += __shfl_xor_sync(0xffffffffu, s0, 1); s0 += __shfl_xor_sync(0xffffffffu, s0, 2);
        s1 += __shfl_xor_sync(0xffffffffu, s1, 1); s1 += __shfl_xor_sync(0xffffffffu, s1, 2);
        const float i0 = 1.f / s0, i1 = 1.f / s1;
#pragma unroll
        for (int nt = 0; nt < 7; nt++) {
            lo[nt][0] *= i0; lo[nt][1] *= i0;
            hi[nt][0] *= i1; hi[nt][1] *= i1;
        }

        float o[4][4];
#pragma unroll
        for (int nf = 0; nf < 4; nf++)
#pragma unroll
            for (int e = 0; e < 4; e++) o[nf][e] = 0.f;
        const int sA = tig >> 1, sB = sA + 2;
        const bool od = (tig & 1);
#pragma unroll
        for (int kt = 0; kt < 7; kt++) {
            float l0a = __shfl_sync(0xffffffffu, lo[kt][0], sA, 4);
            float l1a = __shfl_sync(0xffffffffu, lo[kt][1], sA, 4);
            float l0b = __shfl_sync(0xffffffffu, lo[kt][0], sB, 4);
            float l1b = __shfl_sync(0xffffffffu, lo[kt][1], sB, 4);
            float h0a = __shfl_sync(0xffffffffu, hi[kt][0], sA, 4);
            float h1a = __shfl_sync(0xffffffffu, hi[kt][1], sA, 4);
            float h0b = __shfl_sync(0xffffffffu, hi[kt][0], sB, 4);
            float h1b = __shfl_sync(0xffffffffu, hi[kt][1], sB, 4);
            uint32_t ap[4];
            ap[0] = f2tf(od ? l1a : l0a);
            ap[1] = f2tf(od ? h1a : h0a);
            ap[2] = f2tf(od ? l1b : l0b);
            ap[3] = f2tf(od ? h1b : h0b);
#pragma unroll
            for (int nf = 0; nf < 4; nf++) {
                uint2 vv = vp2[((h * 4 + nf) * 7 + kt) * 32 + lane];
                mma8(o[nf], ap, vv.x, vv.y);
            }
        }
#pragma unroll
        for (int nf = 0; nf < 4; nf++) {
            const int col = h * 32 + nf * 8 + 2 * tig;
            if (v0) *(float2*)&g_ao[(row0 + r0) * DIM + col] = make_float2(o[nf][0], o[nf][1]);
            if (v1) *(float2*)&g_ao[(row0 + r1) * DIM + col] = make_float2(o[nf][2], o[nf][3]);
        }
    }
}

extern "C" void kernel_launch(void* const* d_in, const int* in_sizes, int n_in,
                              void* d_out, int out_size)
{
    const float* x      = (const float*)d_in[0];
    const float* mask   = (const float*)d_in[1];
    const float* w_qkv  = (const float*)d_in[2];
    const float* b_qkv  = (const float*)d_in[3];
    const float* btab   = (const float*)d_in[4];
    const float* w_proj = (const float*)d_in[5];
    const float* b_proj = (const float*)d_in[6];
    const int*   relidx = (const int*)  d_in[7];
    float* out = (float*)d_out;

    cudaFuncSetAttribute(gemm_k128<0>, cudaFuncAttributeMaxDynamicSharedMemorySize,
                         GEMM_SMEMF * 4);
    cudaFuncSetAttribute(gemm_k128<1>, cudaFuncAttributeMaxDynamicSharedMemorySize,
                         GEMM_SMEMF * 4);
    cudaFuncSetAttribute(attn_kernel, cudaFuncAttributeMaxDynamicSharedMemorySize,
                         ATTN_SMEMF * 4);

    prep_kernel<<<128, 512>>>(w_qkv, w_proj);
    prep_bm<<<1274, 512>>>(mask, btab, relidx);
    gemm_k128<0><<<3136, 256, GEMM_SMEMF * 4>>>(x, b_qkv, nullptr);
    attn_kernel<<<NWIN, 256, ATTN_SMEMF * 4>>>(0);
    gemm_k128<1><<<3136, 256, GEMM_SMEMF * 4>>>(nullptr, b_proj, out);
}

// round 14
// speedup vs baseline: 1.0638x; 1.0638x over previous
#include <cuda_runtime.h>
#include <cuda_fp16.h>
#include <cstdint>

#define NTOK   49
#define DIM    128
#define NWIN   4096
#define SCALE  0.17677669529663687f

// ---- global scratch (static __device__, no allocation) ----
__device__ float g_wq[49152];                      // w_qkv, tf32 B-frag-packed (lane-ordered)
__device__ float g_wp[16384];                      // w_proj, tf32 B-frag-packed
__device__ float g_qkv[77070336];                  // [200704][384]  Q(scaled)|K|V raw
__device__ float g_ao[25690112];                   // [200704][128]  attention output raw
__device__ __align__(16) uint16_t g_bm[652288];    // [64][4][49][52] bf16 bias+mask

__device__ __forceinline__ uint32_t f2tf(float f) {
    uint32_t u;
    asm("cvt.rna.tf32.f32 %0, %1;" : "=r"(u) : "f"(f));
    return u;
}
__device__ __forceinline__ void mma8(float* c, const uint32_t* a, uint32_t b0, uint32_t b1) {
    asm("mma.sync.aligned.m16n8k8.row.col.f32.tf32.tf32.f32 "
        "{%0,%1,%2,%3},{%4,%5,%6,%7},{%8,%9},{%0,%1,%2,%3};"
        : "+f"(c[0]), "+f"(c[1]), "+f"(c[2]), "+f"(c[3])
        : "r"(a[0]), "r"(a[1]), "r"(a[2]), "r"(a[3]), "r"(b0), "r"(b1));
}
__device__ __forceinline__ void mma16h(float* c, uint32_t a0, uint32_t a1,
                                       uint32_t a2, uint32_t a3,
                                       uint32_t b0, uint32_t b1) {
    asm("mma.sync.aligned.m16n8k16.row.col.f32.f16.f16.f32 "
        "{%0,%1,%2,%3},{%4,%5,%6,%7},{%8,%9},{%0,%1,%2,%3};"
        : "+f"(c[0]), "+f"(c[1]), "+f"(c[2]), "+f"(c[3])
        : "r"(a0), "r"(a1), "r"(a2), "r"(a3), "r"(b0), "r"(b1));
}
__device__ __forceinline__ uint32_t h2pack(float lo, float hi) {
    __half2 h = __floats2half2_rn(lo, hi);
    return *reinterpret_cast<uint32_t*>(&h);
}
__device__ __forceinline__ void cpa16(uint32_t s, const void* g) {
    asm volatile("cp.async.cg.shared.global [%0], [%1], 16;" :: "r"(s), "l"(g));
}
__device__ __forceinline__ uint32_t smem_u32(const void* p) {
    uint32_t a;
    asm("{ .reg .u64 t; cvta.to.shared.u64 t, %1; cvt.u32.u64 %0, t; }" : "=r"(a) : "l"(p));
    return a;
}
__device__ __forceinline__ uint16_t f2bf(float f) {
    uint32_t u = __float_as_uint(f);
    return (uint16_t)((u + 0x7fffu + ((u >> 16) & 1u)) >> 16);
}

// ---- prep: pack weights into tf32 B-fragment order (lane-ordered) ----
__global__ void prep_kernel(const float* __restrict__ wq, const float* __restrict__ wp) {
    int o = blockIdx.x * blockDim.x + threadIdx.x;        // 65536 total
    int oo = (o < 49152) ? o : o - 49152;
    int slot = oo & 3;
    int lane = (oo >> 2) & 31;
    int kt   = (oo >> 7) & 15;
    int nt   = oo >> 11;
    int tig = lane & 3, gid = lane >> 2;
    int k = kt * 8 + tig + 4 * (slot & 1);
    int n = nt * 16 + gid + 8 * (slot >> 1);
    if (o < 49152) g_wq[oo] = __uint_as_float(f2tf(wq[k * 384 + n]));
    else           g_wp[oo] = __uint_as_float(f2tf(wp[k * 128 + n]));
}

// ---- prep_bm: bm[w][h][r][c52] = btab[ri[r,c],h] + mask[w,r,c]  (bf16) ----
__global__ void prep_bm(const float* __restrict__ mask, const float* __restrict__ btab,
                        const int* __restrict__ relidx) {
    int o = blockIdx.x * blockDim.x + threadIdx.x;        // 652288 total
    if (o >= 652288) return;
    int c = o % 52;
    int t = o / 52;
    int r = t % 49; t /= 49;
    int h = t & 3;
    int w = t >> 2;
    float v = 0.f;
    if (c < 49)
        v = btab[relidx[r * 49 + c] * 4 + h] + mask[w * 2401 + r * 49 + c];
    g_bm[o] = f2bf(v);
}

// ============================================================
// GEMM: C[64 x NO] = A * B_packed + bias, K=128, NS slices of 128
// ============================================================
#define GA_LD 132
#define GS_B  8448
#define GS_BS 24832
#define GEMM_SMEMF 25216           // 100864 B -> 2 blocks/SM

template<int MODE>
__global__ void __launch_bounds__(256, 2)
gemm_k128(const float* __restrict__ Aext, const float* __restrict__ bias,
          float* __restrict__ Cext)
{
    extern __shared__ float sm[];
    float* bs = sm + GS_BS;
    const int tid = threadIdx.x, wid = tid >> 5, lane = tid & 31;
    const int gid = lane >> 2, tig = lane & 3;
    const uint32_t su = smem_u32(sm);

    const float* A  = (MODE == 0) ? Aext : g_ao;
    const float* Bp = (MODE == 0) ? g_wq : g_wp;
    const int    NO = (MODE == 0) ? 384 : 128;
    const int    NS = (MODE == 0) ? 3 : 1;
    float*       C  = (MODE == 0) ? g_qkv : Cext;

    const size_t arow0 = (size_t)blockIdx.x * 64;
    for (int i = tid; i < 2048; i += 256) {               // raw A 64x128
        int r = i >> 5, c4 = i & 31;
        cpa16(su + (r * GA_LD + c4 * 4) * 4, A + (arow0 + r) * DIM + c4 * 4);
    }
    for (int i = tid; i < NO / 4; i += 256)               // bias
        cpa16(su + (GS_BS + i * 4) * 4, bias + i * 4);
    asm volatile("cp.async.commit_group;");
    for (int i = tid; i < 4096; i += 256)                 // B slice 0
        cpa16(su + (GS_B + i * 4) * 4, Bp + i * 4);
    asm volatile("cp.async.commit_group;");
    asm volatile("cp.async.wait_group 1;");
    __syncthreads();

    // ---- one-time in-smem A repack, lane-ordered ----
    float4 stg[8];
#pragma unroll
    for (int j = 0; j < 8; j++) {
        const int u = tid + 256 * j;
        const int mt = u >> 9, kt = (u >> 5) & 15;
        const int l = u & 31, gd = (l >> 2) & 7, tg = l & 3;
        const int r = mt * 16 + gd, c = kt * 8 + tg;
        stg[j].x = __uint_as_float(f2tf(sm[r * GA_LD + c]));
        stg[j].y = __uint_as_float(f2tf(sm[(r + 8) * GA_LD + c]));
        stg[j].z = __uint_as_float(f2tf(sm[r * GA_LD + c + 4]));
        stg[j].w = __uint_as_float(f2tf(sm[(r + 8) * GA_LD + c + 4]));
    }
    __syncthreads();
    {
        float4* As4w = (float4*)sm;
#pragma unroll
        for (int j = 0; j < 8; j++) As4w[tid + 256 * j] = stg[j];
    }
    asm volatile("cp.async.wait_group 0;");
    __syncthreads();

    const int mw = wid & 1, nw = wid >> 1;
    const uint4* As4 = (const uint4*)sm;
    const uint4* Bs4 = (const uint4*)(sm + GS_B);

#pragma unroll 1
    for (int t = 0; t < NS; t++) {
        float c[2][4][4];
#pragma unroll
        for (int f = 0; f < 2; f++)
#pragma unroll
            for (int j = 0; j < 4; j++)
#pragma unroll
                for (int e = 0; e < 4; e++) c[f][j][e] = 0.f;

#pragma unroll
        for (int kt = 0; kt < 16; kt++) {
            uint4 av0 = As4[((mw * 2 + 0) * 16 + kt) * 32 + lane];
            uint4 av1 = As4[((mw * 2 + 1) * 16 + kt) * 32 + lane];
            uint4 bv0 = Bs4[((nw * 2 + 0) * 16 + kt) * 32 + lane];
            uint4 bv1 = Bs4[((nw * 2 + 1) * 16 + kt) * 32 + lane];
            mma8(c[0][0], (const uint32_t*)&av0, bv0.x, bv0.y);
            mma8(c[0][1], (const uint32_t*)&av0, bv0.z, bv0.w);
            mma8(c[0][2], (const uint32_t*)&av0, bv1.x, bv1.y);
            mma8(c[0][3], (const uint32_t*)&av0, bv1.z, bv1.w);
            mma8(c[1][0], (const uint32_t*)&av1, bv0.x, bv0.y);
            mma8(c[1][1], (const uint32_t*)&av1, bv0.z, bv0.w);
            mma8(c[1][2], (const uint32_t*)&av1, bv1.x, bv1.y);
            mma8(c[1][3], (const uint32_t*)&av1, bv1.z, bv1.w);
        }

        __syncthreads();
        if (t + 1 < NS) {
            const float* Bn = Bp + (t + 1) * 16384;
            for (int i = tid; i < 4096; i += 256)
                cpa16(su + (GS_B + i * 4) * 4, Bn + i * 4);
            asm volatile("cp.async.commit_group;");
        }

        const int   cb = t * 128;
        const float sc = (MODE == 0 && t == 0) ? SCALE : 1.f;
#pragma unroll
        for (int f = 0; f < 2; f++) {
            const size_t r0 = arow0 + (mw * 2 + f) * 16 + gid;
#pragma unroll
            for (int j = 0; j < 4; j++) {
                const int cl = nw * 32 + j * 8 + 2 * tig;
                const float b0 = bs[cb + cl], b1 = bs[cb + cl + 1];
                const int cg = cb + cl;
                *(float2*)&C[r0 * NO + cg] =
                    make_float2((c[f][j][0] + b0) * sc, (c[f][j][1] + b1) * sc);
                *(float2*)&C[(r0 + 8) * NO + cg] =
                    make_float2((c[f][j][2] + b0) * sc, (c[f][j][3] + b1) * sc);
            }
        }
        if (t + 1 < NS) {
            asm volatile("cp.async.wait_group 0;");
            __syncthreads();
        }
    }
}

// ============================================================
// Attention: K tf32 frags + V fp16 B-frags in smem; register
// softmax (bf16 fused bias+mask); P C-frags feed fp16 PV mma
// directly (NO permute); 1/sum folded into output store.
// smem: Q raw 56x132 | KV staging 49x260 (repacked in place) | bm
// ============================================================
#define Q_LD   132
#define AS_KV  7392
#define AS_BM  20132               // AS_KV + 12740 (staging extent)
#define ATTN_SMEMF 25228           // 100912 B -> 2 blocks/SM
#define KV_REP 22                  // (3584 K + 2048 V) uint2 / 256 thr

__global__ void __launch_bounds__(256, 2)
attn_kernel(int dummy)
{
    extern __shared__ float sm[];
    float* qs = sm;
    const uint32_t* bm32 = (const uint32_t*)(sm + AS_BM);
    const int tid = threadIdx.x, wid = tid >> 5, lane = tid & 31;
    const int gid = lane >> 2, tig = lane & 3;
    const uint32_t su = smem_u32(sm);

    const int wb = blockIdx.x;
    const size_t row0 = (size_t)wb * NTOK;
    for (int i = tid; i < 1568; i += 256) {               // Q raw 49x128
        int r = i >> 5, c4 = i & 31;
        cpa16(su + (r * Q_LD + c4 * 4) * 4, g_qkv + (row0 + r) * 384 + c4 * 4);
    }
    for (int i = tid; i < 3136; i += 256) {               // KV raw 49x256, stride 260
        int r = i >> 6, c4 = i & 63;
        cpa16(su + (AS_KV + r * 260 + c4 * 4) * 4, g_qkv + (row0 + r) * 384 + 128 + c4 * 4);
    }
    const int w = wb & 63;
    {
        const char* bsrc = (const char*)g_bm + (size_t)w * 20384;
        for (int i = tid; i < 1274; i += 256)
            cpa16(su + AS_BM * 4 + i * 16, bsrc + i * 16);
    }
    for (int i = tid; i < 7 * Q_LD; i += 256) qs[49 * Q_LD + i] = 0.f;  // zero Q rows 49..55
    asm volatile("cp.async.commit_group;\n\tcp.async.wait_group 0;");
    __syncthreads();

    // ---- one-time K/V repack (register-staged, writes over staging) ----
    // K uint2 idx ((h*7+nt)*4+kt)*32+l : tf32 {K[nt*8+gd][kt*8+tg], [col+4]}
    // V uint2 idx 3584+((h*4+nf)*4+j)*32+l : fp16 B-frags for m16n8k16
    //   .x = h2(V[16j+2tg][col], V[16j+2tg+1][col])
    //   .y = h2(V[16j+8+2tg][col], V[16j+8+2tg+1][col]),  col = h*32+nf*8+gd
    {
        const float* stage = sm + AS_KV;
        float2 stg[KV_REP];
#pragma unroll
        for (int j = 0; j < KV_REP; j++) {
            const int u = tid + 256 * j;
            if (u < 3584) {
                const int l = u & 31, kt = (u >> 5) & 3, t2 = u >> 7;
                const int nt = t2 % 7, h2 = t2 / 7;
                const int gd = l >> 2, tg = l & 3;
                const int row = nt * 8 + gd, col = h2 * 32 + kt * 8 + tg;
                float a = (row < NTOK) ? stage[row * 260 + col] : 0.f;
                float b = (row < NTOK) ? stage[row * 260 + col + 4] : 0.f;
                stg[j].x = __uint_as_float(f2tf(a));
                stg[j].y = __uint_as_float(f2tf(b));
            } else {
                const int v = u - 3584;
                const int l = v & 31, idx = v >> 5;
                const int j4 = idx & 3, nf = (idx >> 2) & 3, h2 = idx >> 4;
                const int gd = l >> 2, tg = l & 3;
                const int col = 128 + h2 * 32 + nf * 8 + gd;
                const int ra = 16 * j4 + 2 * tg;
                float fa = (ra     < NTOK) ? stage[ ra      * 260 + col] : 0.f;
                float fb = (ra + 1 < NTOK) ? stage[(ra + 1) * 260 + col] : 0.f;
                float fc = (ra + 8 < NTOK) ? stage[(ra + 8) * 260 + col] : 0.f;
                float fd = (ra + 9 < NTOK) ? stage[(ra + 9) * 260 + col] : 0.f;
                stg[j].x = __uint_as_float(h2pack(fa, fb));
                stg[j].y = __uint_as_float(h2pack(fc, fd));
            }
        }
        __syncthreads();
        float2* kv2 = (float2*)(sm + AS_KV);
#pragma unroll
        for (int j = 0; j < KV_REP; j++) kv2[tid + 256 * j] = stg[j];
    }
    __syncthreads();

    const uint2* kp2 = (const uint2*)(sm + AS_KV);
    const uint2* vp2 = kp2 + 3584;
    const int h = wid & 3, mt = wid >> 2;
#pragma unroll 1
    for (int sub = 0; sub < 2; sub++) {
        const int m0 = (mt * 2 + sub) * 16;
        const bool hiO = (m0 == 48);

        uint32_t aq[4][4];
#pragma unroll
        for (int kt = 0; kt < 4; kt++) {
            const float* p = qs + (m0 + gid) * Q_LD + h * 32 + kt * 8 + tig;
            aq[kt][0] = f2tf(p[0]);
            aq[kt][2] = f2tf(p[4]);
            aq[kt][1] = hiO ? 0u : f2tf(p[8 * Q_LD]);
            aq[kt][3] = hiO ? 0u : f2tf(p[8 * Q_LD + 4]);
        }
        float s_[7][4];
#pragma unroll
        for (int nt = 0; nt < 7; nt++) {
            float cc[4] = {0.f, 0.f, 0.f, 0.f};
#pragma unroll
            for (int kt = 0; kt < 4; kt++) {
                uint2 kv = kp2[((h * 7 + nt) * 4 + kt) * 32 + lane];
                mma8(cc, aq[kt], kv.x, kv.y);
            }
#pragma unroll
            for (int e = 0; e < 4; e++) s_[nt][e] = cc[e];
        }

        const int r0 = m0 + gid, r1 = r0 + 8;
        const bool v0 = r0 < NTOK, v1 = r1 < NTOK;
        const int br0 = (h * 49 + (v0 ? r0 : 0)) * 26;
        const int br1 = (h * 49 + (v1 ? r1 : 0)) * 26;
        float lo[7][2], hi[7][2];
        float mx0 = -1e30f, mx1 = -1e30f;
#pragma unroll
        for (int nt = 0; nt < 7; nt++) {
            const int cc0 = nt * 8 + 2 * tig;
            const uint32_t bv0 = bm32[br0 + nt * 4 + tig];
            const uint32_t bv1 = bm32[br1 + nt * 4 + tig];
            const float b00 = __uint_as_float(bv0 << 16);
            const float b01 = __uint_as_float(bv0 & 0xffff0000u);
            const float b10 = __uint_as_float(bv1 << 16);
            const float b11 = __uint_as_float(bv1 & 0xffff0000u);
            lo[nt][0] = (v0 && cc0     < NTOK) ? s_[nt][0] + b00 : -1e30f;
            lo[nt][1] = (v0 && cc0 + 1 < NTOK) ? s_[nt][1] + b01 : -1e30f;
            hi[nt][0] = (v1 && cc0     < NTOK) ? s_[nt][2] + b10 : -1e30f;
            hi[nt][1] = (v1 && cc0 + 1 < NTOK) ? s_[nt][3] + b11 : -1e30f;
            mx0 = fmaxf(mx0, fmaxf(lo[nt][0], lo[nt][1]));
            mx1 = fmaxf(mx1, fmaxf(hi[nt][0], hi[nt][1]));
        }
        mx0 = fmaxf(mx0, __shfl_xor_sync(0xffffffffu, mx0, 1));
        mx0 = fmaxf(mx0, __shfl_xor_sync(0xffffffffu, mx0, 2));
        mx1 = fmaxf(mx1, __shfl_xor_sync(0xffffffffu, mx1, 1));
        mx1 = fmaxf(mx1, __shfl_xor_sync(0xffffffffu, mx1, 2));
        float s0 = 0.f, s1 = 0.f;
#pragma unroll
        for (int nt = 0; nt < 7; nt++)
#pragma unroll
            for (int s = 0; s < 2; s++) {
                float e0 = __expf(lo[nt][s] - mx0);
                float e1 = __expf(hi[nt][s] - mx1);
                lo[nt][s] = e0; hi[nt][s] = e1;
                s0 += e0; s1 += e1;
            }
        s0 += __shfl_xor_sync(0xffffffffu, s0, 1); s0 += __shfl_xor_sync(0xffffffffu, s0, 2);
        s1 += __shfl_xor_sync(0xffffffffu, s1, 1); s1 += __shfl_xor_sync(0xffffffffu, s1, 2);
        const float i0 = 1.f / s0, i1 = 1.f / s1;

        // ---- PV: C-frags ARE fp16 A-frags; no permute, no normalize ----
        float o[4][4];
#pragma unroll
        for (int nf = 0; nf < 4; nf++)
#pragma unroll
            for (int e = 0; e < 4; e++) o[nf][e] = 0.f;
#pragma unroll
        for (int j = 0; j < 4; j++) {
            const uint32_t a0 = h2pack(lo[2 * j][0], lo[2 * j][1]);
            const uint32_t a1 = h2pack(hi[2 * j][0], hi[2 * j][1]);
            const uint32_t a2 = (j < 3) ? h2pack(lo[2 * j + 1][0], lo[2 * j + 1][1]) : 0u;
            const uint32_t a3 = (j < 3) ? h2pack(hi[2 * j + 1][0], hi[2 * j + 1][1]) : 0u;
#pragma unroll
            for (int nf = 0; nf < 4; nf++) {
                uint2 vv = vp2[((h * 4 + nf) * 4 + j) * 32 + lane];
                mma16h(o[nf], a0, a1, a2, a3, vv.x, vv.y);
            }
        }
#pragma unroll
        for (int nf = 0; nf < 4; nf++) {
            const int col = h * 32 + nf * 8 + 2 * tig;
            if (v0) *(float2*)&g_ao[(row0 + r0) * DIM + col] =
                make_float2(o[nf][0] * i0, o[nf][1] * i0);
            if (v1) *(float2*)&g_ao[(row0 + r1) * DIM + col] =
                make_float2(o[nf][2] * i1, o[nf][3] * i1);
        }
    }
}

extern "C" void kernel_launch(void* const* d_in, const int* in_sizes, int n_in,
                              void* d_out, int out_size)
{
    const float* x      = (const float*)d_in[0];
    const float* mask   = (const float*)d_in[1];
    const float* w_qkv  = (const float*)d_in[2];
    const float* b_qkv  = (const float*)d_in[3];
    const float* btab   = (const float*)d_in[4];
    const float* w_proj = (const float*)d_in[5];
    const float* b_proj = (const float*)d_in[6];
    const int*   relidx = (const int*)  d_in[7];
    float* out = (float*)d_out;

    cudaFuncSetAttribute(gemm_k128<0>, cudaFuncAttributeMaxDynamicSharedMemorySize,
                         GEMM_SMEMF * 4);
    cudaFuncSetAttribute(gemm_k128<1>, cudaFuncAttributeMaxDynamicSharedMemorySize,
                         GEMM_SMEMF * 4);
    cudaFuncSetAttribute(attn_kernel, cudaFuncAttributeMaxDynamicSharedMemorySize,
                         ATTN_SMEMF * 4);

    prep_kernel<<<128, 512>>>(w_qkv, w_proj);
    prep_bm<<<1274, 512>>>(mask, btab, relidx);
    gemm_k128<0><<<3136, 256, GEMM_SMEMF * 4>>>(x, b_qkv, nullptr);
    attn_kernel<<<NWIN, 256, ATTN_SMEMF * 4>>>(0);
    gemm_k128<1><<<3136, 256, GEMM_SMEMF * 4>>>(nullptr, b_proj, out);
}

// round 15
// speedup vs baseline: 1.1582x; 1.0888x over previous
#include <cuda_runtime.h>
#include <cuda_fp16.h>
#include <cstdint>

#define NTOK   49
#define DIM    128
#define NWIN   4096
#define SCALE  0.17677669529663687f

// ---- global scratch (static __device__, no allocation) ----
__device__ float g_wq[49152];                      // w_qkv, tf32 B-frag-packed (lane-ordered)
__device__ float g_wp[16384];                      // w_proj, tf32 B-frag-packed
__device__ __align__(16) __half g_qkv[77070336];   // [200704][384] fp16 Q(scaled)|K|V
__device__ __align__(16) __half g_ao[25690112];    // [200704][128] fp16 attention output
__device__ __align__(16) uint16_t g_bm[652288];    // [64][4][49][52] bf16 bias+mask

__device__ __forceinline__ uint32_t f2tf(float f) {
    uint32_t u;
    asm("cvt.rna.tf32.f32 %0, %1;" : "=r"(u) : "f"(f));
    return u;
}
__device__ __forceinline__ void mma8(float* c, const uint32_t* a, uint32_t b0, uint32_t b1) {
    asm("mma.sync.aligned.m16n8k8.row.col.f32.tf32.tf32.f32 "
        "{%0,%1,%2,%3},{%4,%5,%6,%7},{%8,%9},{%0,%1,%2,%3};"
        : "+f"(c[0]), "+f"(c[1]), "+f"(c[2]), "+f"(c[3])
        : "r"(a[0]), "r"(a[1]), "r"(a[2]), "r"(a[3]), "r"(b0), "r"(b1));
}
__device__ __forceinline__ void mma16h(float* c, uint32_t a0, uint32_t a1,
                                       uint32_t a2, uint32_t a3,
                                       uint32_t b0, uint32_t b1) {
    asm("mma.sync.aligned.m16n8k16.row.col.f32.f16.f16.f32 "
        "{%0,%1,%2,%3},{%4,%5,%6,%7},{%8,%9},{%0,%1,%2,%3};"
        : "+f"(c[0]), "+f"(c[1]), "+f"(c[2]), "+f"(c[3])
        : "r"(a0), "r"(a1), "r"(a2), "r"(a3), "r"(b0), "r"(b1));
}
__device__ __forceinline__ uint32_t h2pack(float lo, float hi) {
    __half2 h = __floats2half2_rn(lo, hi);
    return *reinterpret_cast<uint32_t*>(&h);
}
__device__ __forceinline__ void cpa16(uint32_t s, const void* g) {
    asm volatile("cp.async.cg.shared.global [%0], [%1], 16;" :: "r"(s), "l"(g));
}
__device__ __forceinline__ uint32_t smem_u32(const void* p) {
    uint32_t a;
    asm("{ .reg .u64 t; cvta.to.shared.u64 t, %1; cvt.u32.u64 %0, t; }" : "=r"(a) : "l"(p));
    return a;
}
__device__ __forceinline__ uint16_t f2bf(float f) {
    uint32_t u = __float_as_uint(f);
    return (uint16_t)((u + 0x7fffu + ((u >> 16) & 1u)) >> 16);
}

// ---- prep: pack weights into tf32 B-fragment order (lane-ordered) ----
__global__ void prep_kernel(const float* __restrict__ wq, const float* __restrict__ wp) {
    int o = blockIdx.x * blockDim.x + threadIdx.x;        // 65536 total
    int oo = (o < 49152) ? o : o - 49152;
    int slot = oo & 3;
    int lane = (oo >> 2) & 31;
    int kt   = (oo >> 7) & 15;
    int nt   = oo >> 11;
    int tig = lane & 3, gid = lane >> 2;
    int k = kt * 8 + tig + 4 * (slot & 1);
    int n = nt * 16 + gid + 8 * (slot >> 1);
    if (o < 49152) g_wq[oo] = __uint_as_float(f2tf(wq[k * 384 + n]));
    else           g_wp[oo] = __uint_as_float(f2tf(wp[k * 128 + n]));
}

// ---- prep_bm: bm[w][h][r][c52] = btab[ri[r,c],h] + mask[w,r,c]  (bf16) ----
__global__ void prep_bm(const float* __restrict__ mask, const float* __restrict__ btab,
                        const int* __restrict__ relidx) {
    int o = blockIdx.x * blockDim.x + threadIdx.x;        // 652288 total
    if (o >= 652288) return;
    int c = o % 52;
    int t = o / 52;
    int r = t % 49; t /= 49;
    int h = t & 3;
    int w = t >> 2;
    float v = 0.f;
    if (c < 49)
        v = btab[relidx[r * 49 + c] * 4 + h] + mask[w * 2401 + r * 49 + c];
    g_bm[o] = f2bf(v);
}

// ============================================================
// GEMM: C[64 x NO] = A * B_packed + bias, K=128, NS slices of 128
// MODE 0: A=x fp32,   C=g_qkv fp16 (NO=384, NS=3, slice0 scaled)
// MODE 1: A=g_ao fp16, C=out fp32  (NO=128, NS=1)
// ============================================================
#define GA_LD 132
#define GS_B  8448
#define GS_BS 24832
#define GEMM_SMEMF 25216           // 100864 B -> 2 blocks/SM

template<int MODE>
__global__ void __launch_bounds__(256, 2)
gemm_k128(const float* __restrict__ Aext, const float* __restrict__ bias,
          float* __restrict__ Cext)
{
    extern __shared__ float sm[];
    float* bs = sm + GS_BS;
    const int tid = threadIdx.x, wid = tid >> 5, lane = tid & 31;
    const int gid = lane >> 2, tig = lane & 3;
    const uint32_t su = smem_u32(sm);

    const float* Bp = (MODE == 0) ? g_wq : g_wp;
    const int    NO = (MODE == 0) ? 384 : 128;
    const int    NS = (MODE == 0) ? 3 : 1;

    const size_t arow0 = (size_t)blockIdx.x * 64;
    if (MODE == 0) {
        for (int i = tid; i < 2048; i += 256) {           // raw A fp32 64x128
            int r = i >> 5, c4 = i & 31;
            cpa16(su + (r * GA_LD + c4 * 4) * 4, Aext + (arow0 + r) * DIM + c4 * 4);
        }
    } else {
        for (int i = tid; i < 1024; i += 256) {           // raw A fp16 64x128, stride 136 halves
            int r = i >> 4, c8 = i & 15;
            cpa16(su + r * 272 + c8 * 16, g_ao + (arow0 + r) * DIM + c8 * 8);
        }
    }
    for (int i = tid; i < NO / 4; i += 256)               // bias
        cpa16(su + (GS_BS + i * 4) * 4, bias + i * 4);
    asm volatile("cp.async.commit_group;");
    for (int i = tid; i < 4096; i += 256)                 // B slice 0
        cpa16(su + (GS_B + i * 4) * 4, Bp + i * 4);
    asm volatile("cp.async.commit_group;");
    asm volatile("cp.async.wait_group 1;");
    __syncthreads();

    // ---- one-time in-smem A repack, lane-ordered ----
    float4 stg[8];
#pragma unroll
    for (int j = 0; j < 8; j++) {
        const int u = tid + 256 * j;
        const int mt = u >> 9, kt = (u >> 5) & 15;
        const int l = u & 31, gd = (l >> 2) & 7, tg = l & 3;
        const int r = mt * 16 + gd, c = kt * 8 + tg;
        if (MODE == 0) {
            stg[j].x = __uint_as_float(f2tf(sm[r * GA_LD + c]));
            stg[j].y = __uint_as_float(f2tf(sm[(r + 8) * GA_LD + c]));
            stg[j].z = __uint_as_float(f2tf(sm[r * GA_LD + c + 4]));
            stg[j].w = __uint_as_float(f2tf(sm[(r + 8) * GA_LD + c + 4]));
        } else {
            const __half* shh = (const __half*)sm;
            stg[j].x = __uint_as_float(f2tf(__half2float(shh[r * 136 + c])));
            stg[j].y = __uint_as_float(f2tf(__half2float(shh[(r + 8) * 136 + c])));
            stg[j].z = __uint_as_float(f2tf(__half2float(shh[r * 136 + c + 4])));
            stg[j].w = __uint_as_float(f2tf(__half2float(shh[(r + 8) * 136 + c + 4])));
        }
    }
    __syncthreads();
    {
        float4* As4w = (float4*)sm;
#pragma unroll
        for (int j = 0; j < 8; j++) As4w[tid + 256 * j] = stg[j];
    }
    asm volatile("cp.async.wait_group 0;");
    __syncthreads();

    const int mw = wid & 1, nw = wid >> 1;
    const uint4* As4 = (const uint4*)sm;
    const uint4* Bs4 = (const uint4*)(sm + GS_B);

#pragma unroll 1
    for (int t = 0; t < NS; t++) {
        float c[2][4][4];
#pragma unroll
        for (int f = 0; f < 2; f++)
#pragma unroll
            for (int j = 0; j < 4; j++)
#pragma unroll
                for (int e = 0; e < 4; e++) c[f][j][e] = 0.f;

#pragma unroll
        for (int kt = 0; kt < 16; kt++) {
            uint4 av0 = As4[((mw * 2 + 0) * 16 + kt) * 32 + lane];
            uint4 av1 = As4[((mw * 2 + 1) * 16 + kt) * 32 + lane];
            uint4 bv0 = Bs4[((nw * 2 + 0) * 16 + kt) * 32 + lane];
            uint4 bv1 = Bs4[((nw * 2 + 1) * 16 + kt) * 32 + lane];
            mma8(c[0][0], (const uint32_t*)&av0, bv0.x, bv0.y);
            mma8(c[0][1], (const uint32_t*)&av0, bv0.z, bv0.w);
            mma8(c[0][2], (const uint32_t*)&av0, bv1.x, bv1.y);
            mma8(c[0][3], (const uint32_t*)&av0, bv1.z, bv1.w);
            mma8(c[1][0], (const uint32_t*)&av1, bv0.x, bv0.y);
            mma8(c[1][1], (const uint32_t*)&av1, bv0.z, bv0.w);
            mma8(c[1][2], (const uint32_t*)&av1, bv1.x, bv1.y);
            mma8(c[1][3], (const uint32_t*)&av1, bv1.z, bv1.w);
        }

        __syncthreads();
        if (t + 1 < NS) {
            const float* Bn = Bp + (t + 1) * 16384;
            for (int i = tid; i < 4096; i += 256)
                cpa16(su + (GS_B + i * 4) * 4, Bn + i * 4);
            asm volatile("cp.async.commit_group;");
        }

        const int   cb = t * 128;
        const float sc = (MODE == 0 && t == 0) ? SCALE : 1.f;
#pragma unroll
        for (int f = 0; f < 2; f++) {
            const size_t r0 = arow0 + (mw * 2 + f) * 16 + gid;
#pragma unroll
            for (int j = 0; j < 4; j++) {
                const int cl = nw * 32 + j * 8 + 2 * tig;
                const float b0 = bs[cb + cl], b1 = bs[cb + cl + 1];
                const int cg = cb + cl;
                if (MODE == 0) {
                    uint32_t* C2 = (uint32_t*)g_qkv;
                    C2[(r0 * 384 + cg) >> 1] =
                        h2pack((c[f][j][0] + b0) * sc, (c[f][j][1] + b1) * sc);
                    C2[((r0 + 8) * 384 + cg) >> 1] =
                        h2pack((c[f][j][2] + b0) * sc, (c[f][j][3] + b1) * sc);
                } else {
                    *(float2*)&Cext[r0 * 128 + cg] =
                        make_float2(c[f][j][0] + b0, c[f][j][1] + b1);
                    *(float2*)&Cext[(r0 + 8) * 128 + cg] =
                        make_float2(c[f][j][2] + b0, c[f][j][3] + b1);
                }
            }
        }
        if (t + 1 < NS) {
            asm volatile("cp.async.wait_group 0;");
            __syncthreads();
        }
    }
}

// ============================================================
// Attention, all-fp16 operands:
//  - QKV staged fp16 row-major (56 rows x 392 halves, rows 49..55 zero)
//  - QK^T via mma.m16n8k16.f16: Q A-frags and K B-frags are contiguous
//    half-pairs in staging -> 1 LDS.32 each, zero cvt, zero repack
//  - V one-time repack to fp16 B-frags (vertical pairs)
//  - register softmax w/ bf16 fused bias+mask; 1/sum folded into store
// smem bytes: ST 43904 | VP 16384 | BM 20384 = 80672 -> 2 blocks/SM
// ============================================================
#define AS_VP_B 43904
#define AS_BM_B 60288
#define ATTN_SMEMB 80672

__global__ void __launch_bounds__(256, 2)
attn_kernel(int dummy)
{
    extern __shared__ float sm[];
    const uint32_t* stw = (const uint32_t*)sm;            // staging as words
    const unsigned short* sts = (const unsigned short*)sm;
    const uint32_t* bm32 = (const uint32_t*)((const char*)sm + AS_BM_B);
    const int tid = threadIdx.x, wid = tid >> 5, lane = tid & 31;
    const int gid = lane >> 2, tig = lane & 3;
    const uint32_t su = smem_u32(sm);

    const int wb = blockIdx.x;
    const size_t row0 = (size_t)wb * NTOK;
    for (int i = tid; i < 2352; i += 256) {               // qkv fp16 49x384, stride 392
        int r = i / 48, c = i % 48;
        cpa16(su + r * 784 + c * 16, g_qkv + (row0 + r) * 384 + c * 8);
    }
    const int w = wb & 63;
    {
        const char* bsrc = (const char*)g_bm + (size_t)w * 20384;
        for (int i = tid; i < 1274; i += 256)
            cpa16(su + AS_BM_B + i * 16, bsrc + i * 16);
    }
    {                                                      // zero rows 49..55
        uint32_t* zw = (uint32_t*)sm;
        for (int i = tid; i < 1372; i += 256) zw[9604 + i] = 0;
    }
    asm volatile("cp.async.commit_group;\n\tcp.async.wait_group 0;");
    __syncthreads();

    // ---- one-time V repack to fp16 B-frags (separate region, no staging overlap) ----
    // uint2 idx ((h*4+nf)*4+j)*32+l :
    //  .x = h2(V[16j+2tg][col], V[16j+2tg+1][col]); .y = rows +8; col = h*32+nf*8+gd
    {
        uint2* vp2w = (uint2*)((char*)sm + AS_VP_B);
        for (int j = 0; j < 8; j++) {
            const int u = tid + 256 * j;
            const int l = u & 31, idx = u >> 5;
            const int j4 = idx & 3, nf = (idx >> 2) & 3, hh = idx >> 4;
            const int gd = l >> 2, tg = l & 3;
            const int col = 256 + hh * 32 + nf * 8 + gd;
            const int ra = 16 * j4 + 2 * tg;
            uint32_t fa = (ra     < NTOK) ? sts[ ra      * 392 + col] : 0u;
            uint32_t fb = (ra + 1 < NTOK) ? sts[(ra + 1) * 392 + col] : 0u;
            uint32_t fc = (ra + 8 < NTOK) ? sts[(ra + 8) * 392 + col] : 0u;
            uint32_t fd = (ra + 9 < NTOK) ? sts[(ra + 9) * 392 + col] : 0u;
            uint2 v;
            v.x = fa | (fb << 16);
            v.y = fc | (fd << 16);
            vp2w[u] = v;
        }
    }
    __syncthreads();

    const uint2* vp2 = (const uint2*)((const char*)sm + AS_VP_B);
    const int h = wid & 3, mt = wid >> 2;
#pragma unroll 1
    for (int sub = 0; sub < 2; sub++) {
        const int m0 = (mt * 2 + sub) * 16;
        const bool hiO = (m0 == 48);

        // Q A-frags: contiguous half-pairs, 1 LDS.32 each
        uint32_t aq[2][4];
#pragma unroll
        for (int kt = 0; kt < 2; kt++) {
            const int base = (m0 + gid) * 196 + h * 16 + kt * 8 + tig;
            aq[kt][0] = stw[base];
            aq[kt][2] = stw[base + 4];
            aq[kt][1] = hiO ? 0u : stw[base + 8 * 196];
            aq[kt][3] = hiO ? 0u : stw[base + 8 * 196 + 4];
        }
        // S = Q @ K^T, fp16 k16 steps
        float s_[7][4];
#pragma unroll
        for (int nt = 0; nt < 7; nt++) {
            float cc[4] = {0.f, 0.f, 0.f, 0.f};
#pragma unroll
            for (int kt = 0; kt < 2; kt++) {
                const int kb = (nt * 8 + gid) * 196 + 64 + h * 16 + kt * 8 + tig;
                mma16h(cc, aq[kt][0], aq[kt][1], aq[kt][2], aq[kt][3],
                       stw[kb], stw[kb + 4]);
            }
#pragma unroll
            for (int e = 0; e < 4; e++) s_[nt][e] = cc[e];
        }

        const int r0 = m0 + gid, r1 = r0 + 8;
        const bool v0 = r0 < NTOK, v1 = r1 < NTOK;
        const int br0 = (h * 49 + (v0 ? r0 : 0)) * 26;
        const int br1 = (h * 49 + (v1 ? r1 : 0)) * 26;
        float lo[7][2], hi[7][2];
        float mx0 = -1e30f, mx1 = -1e30f;
#pragma unroll
        for (int nt = 0; nt < 7; nt++) {
            const int cc0 = nt * 8 + 2 * tig;
            const uint32_t bv0 = bm32[br0 + nt * 4 + tig];
            const uint32_t bv1 = bm32[br1 + nt * 4 + tig];
            const float b00 = __uint_as_float(bv0 << 16);
            const float b01 = __uint_as_float(bv0 & 0xffff0000u);
            const float b10 = __uint_as_float(bv1 << 16);
            const float b11 = __uint_as_float(bv1 & 0xffff0000u);
            lo[nt][0] = (v0 && cc0     < NTOK) ? s_[nt][0] + b00 : -1e30f;
            lo[nt][1] = (v0 && cc0 + 1 < NTOK) ? s_[nt][1] + b01 : -1e30f;
            hi[nt][0] = (v1 && cc0     < NTOK) ? s_[nt][2] + b10 : -1e30f;
            hi[nt][1] = (v1 && cc0 + 1 < NTOK) ? s_[nt][3] + b11 : -1e30f;
            mx0 = fmaxf(mx0, fmaxf(lo[nt][0], lo[nt][1]));
            mx1 = fmaxf(mx1, fmaxf(hi[nt][0], hi[nt][1]));
        }
        mx0 = fmaxf(mx0, __shfl_xor_sync(0xffffffffu, mx0, 1));
        mx0 = fmaxf(mx0, __shfl_xor_sync(0xffffffffu, mx0, 2));
        mx1 = fmaxf(mx1, __shfl_xor_sync(0xffffffffu, mx1, 1));
        mx1 = fmaxf(mx1, __shfl_xor_sync(0xffffffffu, mx1, 2));
        float s0 = 0.f, s1 = 0.f;
#pragma unroll
        for (int nt = 0; nt < 7; nt++)
#pragma unroll
            for (int s = 0; s < 2; s++) {
                float e0 = __expf(lo[nt][s] - mx0);
                float e1 = __expf(hi[nt][s] - mx1);
                lo[nt][s] = e0; hi[nt][s] = e1;
                s0 += e0; s1 += e1;
            }
        s0 += __shfl_xor_sync(0xffffffffu, s0, 1); s0 += __shfl_xor_sync(0xffffffffu, s0, 2);
        s1 += __shfl_xor_sync(0xffffffffu, s1, 1); s1 += __shfl_xor_sync(0xffffffffu, s1, 2);
        const float i0 = 1.f / s0, i1 = 1.f / s1;

        // ---- PV: C-frags ARE fp16 A-frags; no permute, no normalize ----
        float o[4][4];
#pragma unroll
        for (int nf = 0; nf < 4; nf++)
#pragma unroll
            for (int e = 0; e < 4; e++) o[nf][e] = 0.f;
#pragma unroll
        for (int j = 0; j < 4; j++) {
            const uint32_t a0 = h2pack(lo[2 * j][0], lo[2 * j][1]);
            const uint32_t a1 = h2pack(hi[2 * j][0], hi[2 * j][1]);
            const uint32_t a2 = (j < 3) ? h2pack(lo[2 * j + 1][0], lo[2 * j + 1][1]) : 0u;
            const uint32_t a3 = (j < 3) ? h2pack(hi[2 * j + 1][0], hi[2 * j + 1][1]) : 0u;
#pragma unroll
            for (int nf = 0; nf < 4; nf++) {
                uint2 vv = vp2[((h * 4 + nf) * 4 + j) * 32 + lane];
                mma16h(o[nf], a0, a1, a2, a3, vv.x, vv.y);
            }
        }
        uint32_t* ao2 = (uint32_t*)g_ao;
#pragma unroll
        for (int nf = 0; nf < 4; nf++) {
            const int col = h * 32 + nf * 8 + 2 * tig;
            if (v0) ao2[((row0 + r0) * DIM + col) >> 1] =
                h2pack(o[nf][0] * i0, o[nf][1] * i0);
            if (v1) ao2[((row0 + r1) * DIM + col) >> 1] =
                h2pack(o[nf][2] * i1, o[nf][3] * i1);
        }
    }
}

extern "C" void kernel_launch(void* const* d_in, const int* in_sizes, int n_in,
                              void* d_out, int out_size)
{
    const float* x      = (const float*)d_in[0];
    const float* mask   = (const float*)d_in[1];
    const float* w_qkv  = (const float*)d_in[2];
    const float* b_qkv  = (const float*)d_in[3];
    const float* btab   = (const float*)d_in[4];
    const float* w_proj = (const float*)d_in[5];
    const float* b_proj = (const float*)d_in[6];
    const int*   relidx = (const int*)  d_in[7];
    float* out = (float*)d_out;

    cudaFuncSetAttribute(gemm_k128<0>, cudaFuncAttributeMaxDynamicSharedMemorySize,
                         GEMM_SMEMF * 4);
    cudaFuncSetAttribute(gemm_k128<1>, cudaFuncAttributeMaxDynamicSharedMemorySize,
                         GEMM_SMEMF * 4);
    cudaFuncSetAttribute(attn_kernel, cudaFuncAttributeMaxDynamicSharedMemorySize,
                         ATTN_SMEMB);

    prep_kernel<<<128, 512>>>(w_qkv, w_proj);
    prep_bm<<<1274, 512>>>(mask, btab, relidx);
    gemm_k128<0><<<3136, 256, GEMM_SMEMF * 4>>>(x, b_qkv, nullptr);
    attn_kernel<<<NWIN, 256, ATTN_SMEMB>>>(0);
    gemm_k128<1><<<3136, 256, GEMM_SMEMF * 4>>>(nullptr, b_proj, out);
}

// round 16
// speedup vs baseline: 1.4876x; 1.2844x over previous
#include <cuda_runtime.h>
#include <cuda_fp16.h>
#include <cstdint>

#define NTOK   49
#define DIM    128
#define NWIN   4096
#define SCALE  0.17677669529663687f

// ---- global scratch (static __device__, no allocation) ----
__device__ __align__(16) float g_wq[49152];        // w_qkv fp16 B-frags (6144 uint4)
__device__ __align__(16) float g_wp[16384];        // w_proj fp16 B-frags (2048 uint4)
__device__ __align__(16) __half g_qkv[77070336];   // [200704][384] fp16 Q(scaled)|K|V
__device__ __align__(16) __half g_ao[25690112];    // [200704][128] fp16 attention output
__device__ __align__(16) uint16_t g_bm[652288];    // [64][4][49][52] bf16 bias+mask

__device__ __forceinline__ void mma16h(float* c, uint32_t a0, uint32_t a1,
                                       uint32_t a2, uint32_t a3,
                                       uint32_t b0, uint32_t b1) {
    asm("mma.sync.aligned.m16n8k16.row.col.f32.f16.f16.f32 "
        "{%0,%1,%2,%3},{%4,%5,%6,%7},{%8,%9},{%0,%1,%2,%3};"
        : "+f"(c[0]), "+f"(c[1]), "+f"(c[2]), "+f"(c[3])
        : "r"(a0), "r"(a1), "r"(a2), "r"(a3), "r"(b0), "r"(b1));
}
__device__ __forceinline__ uint32_t h2pack(float lo, float hi) {
    __half2 h = __floats2half2_rn(lo, hi);
    return *reinterpret_cast<uint32_t*>(&h);
}
__device__ __forceinline__ void cpa16(uint32_t s, const void* g) {
    asm volatile("cp.async.cg.shared.global [%0], [%1], 16;" :: "r"(s), "l"(g));
}
__device__ __forceinline__ uint32_t smem_u32(const void* p) {
    uint32_t a;
    asm("{ .reg .u64 t; cvta.to.shared.u64 t, %1; cvt.u32.u64 %0, t; }" : "=r"(a) : "l"(p));
    return a;
}
__device__ __forceinline__ uint16_t f2bf(float f) {
    uint32_t u = __float_as_uint(f);
    return (uint16_t)((u + 0x7fffu + ((u >> 16) & 1u)) >> 16);
}

// ---- prep: pack weights into fp16 B-frag uint4s ----
// uint4 idx (wq): ((s*8+nt)*8+kt)*32+l ; (wp): (nt*8+kt)*32+l
// .x=h2(W[k0][n],W[k0+1][n]) .y=h2(W[k0+8][n],W[k0+9][n]) .z,.w = n+8
//   k0 = kt*16+2*tg, n = nbase+nt*16+gd
__global__ void prep_kernel(const float* __restrict__ wq, const float* __restrict__ wp) {
    int o = blockIdx.x * blockDim.x + threadIdx.x;        // 8192 uint4
    const float* W;
    int ncols, nbase, rem;
    if (o < 6144) { W = wq; ncols = 384; nbase = (o >> 11) * 128; rem = o & 2047; }
    else          { W = wp; ncols = 128; nbase = 0;               rem = o - 6144; }
    const int nt = rem >> 8, kt = (rem >> 5) & 7, l = rem & 31;
    const int gd = l >> 2, tg = l & 3;
    const int n = nbase + nt * 16 + gd;
    const int k0 = kt * 16 + 2 * tg;
    uint4 v;
    v.x = h2pack(W[k0 * ncols + n],           W[(k0 + 1) * ncols + n]);
    v.y = h2pack(W[(k0 + 8) * ncols + n],     W[(k0 + 9) * ncols + n]);
    v.z = h2pack(W[k0 * ncols + n + 8],       W[(k0 + 1) * ncols + n + 8]);
    v.w = h2pack(W[(k0 + 8) * ncols + n + 8], W[(k0 + 9) * ncols + n + 8]);
    if (o < 6144) ((uint4*)g_wq)[o] = v;
    else          ((uint4*)g_wp)[o - 6144] = v;
}

// ---- prep_bm: bm[w][h][r][c52] = btab[ri[r,c],h] + mask[w,r,c]  (bf16) ----
__global__ void prep_bm(const float* __restrict__ mask, const float* __restrict__ btab,
                        const int* __restrict__ relidx) {
    int o = blockIdx.x * blockDim.x + threadIdx.x;        // 652288 total
    if (o >= 652288) return;
    int c = o % 52;
    int t = o / 52;
    int r = t % 49; t /= 49;
    int h = t & 3;
    int w = t >> 2;
    float v = 0.f;
    if (c < 49)
        v = btab[relidx[r * 49 + c] * 4 + h] + mask[w * 2401 + r * 49 + c];
    g_bm[o] = f2bf(v);
}

// ============================================================
// GEMM (fp16 mma): C[64 x NO] = A * B + bias, K=128, NS slices
// MODE 0: A=x fp32,   C=g_qkv fp16 (NO=384, NS=3, slice0 scaled)
// MODE 1: A=g_ao fp16, C=out fp32  (NO=128, NS=1)
// smem words: staging/Apack 8448 | B 8192 | bias 384  -> 68096 B
// ============================================================
#define GA_LD 132
#define GS_B  8448
#define GS_BS 16640
#define GEMM_SMEMF 17024

template<int MODE>
__global__ void __launch_bounds__(256, 3)
gemm_k128(const float* __restrict__ Aext, const float* __restrict__ bias,
          float* __restrict__ Cext)
{
    extern __shared__ float sm[];
    float* bs = sm + GS_BS;
    const int tid = threadIdx.x, wid = tid >> 5, lane = tid & 31;
    const int gid = lane >> 2, tig = lane & 3;
    const uint32_t su = smem_u32(sm);

    const float* Bp = (MODE == 0) ? g_wq : g_wp;
    const int    NO = (MODE == 0) ? 384 : 128;
    const int    NS = (MODE == 0) ? 3 : 1;

    const size_t arow0 = (size_t)blockIdx.x * 64;
    if (MODE == 0) {
        for (int i = tid; i < 2048; i += 256) {           // raw A fp32 64x128
            int r = i >> 5, c4 = i & 31;
            cpa16(su + (r * GA_LD + c4 * 4) * 4, Aext + (arow0 + r) * DIM + c4 * 4);
        }
    } else {
        for (int i = tid; i < 1024; i += 256) {           // raw A fp16 64x128, stride 136 halves
            int r = i >> 4, c8 = i & 15;
            cpa16(su + r * 272 + c8 * 16, g_ao + (arow0 + r) * DIM + c8 * 8);
        }
    }
    for (int i = tid; i < NO / 4; i += 256)               // bias
        cpa16(su + (GS_BS + i * 4) * 4, bias + i * 4);
    asm volatile("cp.async.commit_group;");
    for (int i = tid; i < 2048; i += 256)                 // B slice 0 (8192 words)
        cpa16(su + (GS_B + i * 4) * 4, Bp + i * 4);
    asm volatile("cp.async.commit_group;");
    asm volatile("cp.async.wait_group 1;");
    __syncthreads();

    // ---- one-time in-smem A repack to fp16 A-frags (1024 uint4) ----
    // uint4 u: mt=u>>8, kt=(u>>5)&7, l=u&31 (gd=l>>2, tg=l&3)
    // .x=h2(A[r][k0],A[r][k0+1]) .y=rows+8 .z=cols+8 .w=rows+8,cols+8
    uint4 stg[4];
#pragma unroll
    for (int j = 0; j < 4; j++) {
        const int u = tid + 256 * j;
        const int mt = u >> 8, kt = (u >> 5) & 7;
        const int l = u & 31, gd = l >> 2, tg = l & 3;
        const int r = mt * 16 + gd;
        const int k0 = kt * 16 + 2 * tg;
        if (MODE == 0) {
            stg[j].x = h2pack(sm[r * GA_LD + k0],           sm[r * GA_LD + k0 + 1]);
            stg[j].y = h2pack(sm[(r + 8) * GA_LD + k0],     sm[(r + 8) * GA_LD + k0 + 1]);
            stg[j].z = h2pack(sm[r * GA_LD + k0 + 8],       sm[r * GA_LD + k0 + 9]);
            stg[j].w = h2pack(sm[(r + 8) * GA_LD + k0 + 8], sm[(r + 8) * GA_LD + k0 + 9]);
        } else {
            const uint32_t* Sw = (const uint32_t*)sm;      // stride 68 words/row
            stg[j].x = Sw[r * 68 + kt * 8 + tg];
            stg[j].y = Sw[(r + 8) * 68 + kt * 8 + tg];
            stg[j].z = Sw[r * 68 + kt * 8 + tg + 4];
            stg[j].w = Sw[(r + 8) * 68 + kt * 8 + tg + 4];
        }
    }
    __syncthreads();
    {
        uint4* Aw4 = (uint4*)sm;
#pragma unroll
        for (int j = 0; j < 4; j++) Aw4[tid + 256 * j] = stg[j];
    }
    asm volatile("cp.async.wait_group 0;");
    __syncthreads();

    const int mw = wid & 1, nw = wid >> 1;
    const uint4* Ap4 = (const uint4*)sm;
    const uint4* Bp4 = (const uint4*)(sm + GS_B);

#pragma unroll 1
    for (int t = 0; t < NS; t++) {
        float c[2][4][4];
#pragma unroll
        for (int f = 0; f < 2; f++)
#pragma unroll
            for (int j = 0; j < 4; j++)
#pragma unroll
                for (int e = 0; e < 4; e++) c[f][j][e] = 0.f;

#pragma unroll
        for (int kt = 0; kt < 8; kt++) {
            uint4 av0 = Ap4[((mw * 2 + 0) * 8 + kt) * 32 + lane];
            uint4 av1 = Ap4[((mw * 2 + 1) * 8 + kt) * 32 + lane];
            uint4 bv0 = Bp4[((nw * 2 + 0) * 8 + kt) * 32 + lane];
            uint4 bv1 = Bp4[((nw * 2 + 1) * 8 + kt) * 32 + lane];
            mma16h(c[0][0], av0.x, av0.y, av0.z, av0.w, bv0.x, bv0.y);
            mma16h(c[0][1], av0.x, av0.y, av0.z, av0.w, bv0.z, bv0.w);
            mma16h(c[0][2], av0.x, av0.y, av0.z, av0.w, bv1.x, bv1.y);
            mma16h(c[0][3], av0.x, av0.y, av0.z, av0.w, bv1.z, bv1.w);
            mma16h(c[1][0], av1.x, av1.y, av1.z, av1.w, bv0.x, bv0.y);
            mma16h(c[1][1], av1.x, av1.y, av1.z, av1.w, bv0.z, bv0.w);
            mma16h(c[1][2], av1.x, av1.y, av1.z, av1.w, bv1.x, bv1.y);
            mma16h(c[1][3], av1.x, av1.y, av1.z, av1.w, bv1.z, bv1.w);
        }

        __syncthreads();
        if (t + 1 < NS) {
            const float* Bn = Bp + (t + 1) * 8192;
            for (int i = tid; i < 2048; i += 256)
                cpa16(su + (GS_B + i * 4) * 4, Bn + i * 4);
            asm volatile("cp.async.commit_group;");
        }

        const int   cb = t * 128;
        const float sc = (MODE == 0 && t == 0) ? SCALE : 1.f;
#pragma unroll
        for (int f = 0; f < 2; f++) {
            const size_t r0 = arow0 + (mw * 2 + f) * 16 + gid;
#pragma unroll
            for (int j = 0; j < 4; j++) {
                const int cl = nw * 32 + j * 8 + 2 * tig;
                const float b0 = bs[cb + cl], b1 = bs[cb + cl + 1];
                const int cg = cb + cl;
                if (MODE == 0) {
                    uint32_t* C2 = (uint32_t*)g_qkv;
                    C2[(r0 * 384 + cg) >> 1] =
                        h2pack((c[f][j][0] + b0) * sc, (c[f][j][1] + b1) * sc);
                    C2[((r0 + 8) * 384 + cg) >> 1] =
                        h2pack((c[f][j][2] + b0) * sc, (c[f][j][3] + b1) * sc);
                } else {
                    *(float2*)&Cext[r0 * 128 + cg] =
                        make_float2(c[f][j][0] + b0, c[f][j][1] + b1);
                    *(float2*)&Cext[(r0 + 8) * 128 + cg] =
                        make_float2(c[f][j][2] + b0, c[f][j][3] + b1);
                }
            }
        }
        if (t + 1 < NS) {
            asm volatile("cp.async.wait_group 0;");
            __syncthreads();
        }
    }
}

// ============================================================
// Attention (unchanged from R15): all-fp16 operands
// ============================================================
#define AS_VP_B 43904
#define AS_BM_B 60288
#define ATTN_SMEMB 80672

__global__ void __launch_bounds__(256, 2)
attn_kernel(int dummy)
{
    extern __shared__ float sm[];
    const uint32_t* stw = (const uint32_t*)sm;
    const unsigned short* sts = (const unsigned short*)sm;
    const uint32_t* bm32 = (const uint32_t*)((const char*)sm + AS_BM_B);
    const int tid = threadIdx.x, wid = tid >> 5, lane = tid & 31;
    const int gid = lane >> 2, tig = lane & 3;
    const uint32_t su = smem_u32(sm);

    const int wb = blockIdx.x;
    const size_t row0 = (size_t)wb * NTOK;
    for (int i = tid; i < 2352; i += 256) {               // qkv fp16 49x384, stride 392
        int r = i / 48, c = i % 48;
        cpa16(su + r * 784 + c * 16, g_qkv + (row0 + r) * 384 + c * 8);
    }
    const int w = wb & 63;
    {
        const char* bsrc = (const char*)g_bm + (size_t)w * 20384;
        for (int i = tid; i < 1274; i += 256)
            cpa16(su + AS_BM_B + i * 16, bsrc + i * 16);
    }
    {
        uint32_t* zw = (uint32_t*)sm;
        for (int i = tid; i < 1372; i += 256) zw[9604 + i] = 0;
    }
    asm volatile("cp.async.commit_group;\n\tcp.async.wait_group 0;");
    __syncthreads();

    {
        uint2* vp2w = (uint2*)((char*)sm + AS_VP_B);
        for (int j = 0; j < 8; j++) {
            const int u = tid + 256 * j;
            const int l = u & 31, idx = u >> 5;
            const int j4 = idx & 3, nf = (idx >> 2) & 3, hh = idx >> 4;
            const int gd = l >> 2, tg = l & 3;
            const int col = 256 + hh * 32 + nf * 8 + gd;
            const int ra = 16 * j4 + 2 * tg;
            uint32_t fa = (ra     < NTOK) ? sts[ ra      * 392 + col] : 0u;
            uint32_t fb = (ra + 1 < NTOK) ? sts[(ra + 1) * 392 + col] : 0u;
            uint32_t fc = (ra + 8 < NTOK) ? sts[(ra + 8) * 392 + col] : 0u;
            uint32_t fd = (ra + 9 < NTOK) ? sts[(ra + 9) * 392 + col] : 0u;
            uint2 v;
            v.x = fa | (fb << 16);
            v.y = fc | (fd << 16);
            vp2w[u] = v;
        }
    }
    __syncthreads();

    const uint2* vp2 = (const uint2*)((const char*)sm + AS_VP_B);
    const int h = wid & 3, mt = wid >> 2;
#pragma unroll 1
    for (int sub = 0; sub < 2; sub++) {
        const int m0 = (mt * 2 + sub) * 16;
        const bool hiO = (m0 == 48);

        uint32_t aq[2][4];
#pragma unroll
        for (int kt = 0; kt < 2; kt++) {
            const int base = (m0 + gid) * 196 + h * 16 + kt * 8 + tig;
            aq[kt][0] = stw[base];
            aq[kt][2] = stw[base + 4];
            aq[kt][1] = hiO ? 0u : stw[base + 8 * 196];
            aq[kt][3] = hiO ? 0u : stw[base + 8 * 196 + 4];
        }
        float s_[7][4];
#pragma unroll
        for (int nt = 0; nt < 7; nt++) {
            float cc[4] = {0.f, 0.f, 0.f, 0.f};
#pragma unroll
            for (int kt = 0; kt < 2; kt++) {
                const int kb = (nt * 8 + gid) * 196 + 64 + h * 16 + kt * 8 + tig;
                mma16h(cc, aq[kt][0], aq[kt][1], aq[kt][2], aq[kt][3],
                       stw[kb], stw[kb + 4]);
            }
#pragma unroll
            for (int e = 0; e < 4; e++) s_[nt][e] = cc[e];
        }

        const int r0 = m0 + gid, r1 = r0 + 8;
        const bool v0 = r0 < NTOK, v1 = r1 < NTOK;
        const int br0 = (h * 49 + (v0 ? r0 : 0)) * 26;
        const int br1 = (h * 49 + (v1 ? r1 : 0)) * 26;
        float lo[7][2], hi[7][2];
        float mx0 = -1e30f, mx1 = -1e30f;
#pragma unroll
        for (int nt = 0; nt < 7; nt++) {
            const int cc0 = nt * 8 + 2 * tig;
            const uint32_t bv0 = bm32[br0 + nt * 4 + tig];
            const uint32_t bv1 = bm32[br1 + nt * 4 + tig];
            const float b00 = __uint_as_float(bv0 << 16);
            const float b01 = __uint_as_float(bv0 & 0xffff0000u);
            const float b10 = __uint_as_float(bv1 << 16);
            const float b11 = __uint_as_float(bv1 & 0xffff0000u);
            lo[nt][0] = (v0 && cc0     < NTOK) ? s_[nt][0] + b00 : -1e30f;
            lo[nt][1] = (v0 && cc0 + 1 < NTOK) ? s_[nt][1] + b01 : -1e30f;
            hi[nt][0] = (v1 && cc0     < NTOK) ? s_[nt][2] + b10 : -1e30f;
            hi[nt][1] = (v1 && cc0 + 1 < NTOK) ? s_[nt][3] + b11 : -1e30f;
            mx0 = fmaxf(mx0, fmaxf(lo[nt][0], lo[nt][1]));
            mx1 = fmaxf(mx1, fmaxf(hi[nt][0], hi[nt][1]));
        }
        mx0 = fmaxf(mx0, __shfl_xor_sync(0xffffffffu, mx0, 1));
        mx0 = fmaxf(mx0, __shfl_xor_sync(0xffffffffu, mx0, 2));
        mx1 = fmaxf(mx1, __shfl_xor_sync(0xffffffffu, mx1, 1));
        mx1 = fmaxf(mx1, __shfl_xor_sync(0xffffffffu, mx1, 2));
        float s0 = 0.f, s1 = 0.f;
#pragma unroll
        for (int nt = 0; nt < 7; nt++)
#pragma unroll
            for (int s = 0; s < 2; s++) {
                float e0 = __expf(lo[nt][s] - mx0);
                float e1 = __expf(hi[nt][s] - mx1);
                lo[nt][s] = e0; hi[nt][s] = e1;
                s0 += e0; s1 += e1;
            }
        s0 += __shfl_xor_sync(0xffffffffu, s0, 1); s0 += __shfl_xor_sync(0xffffffffu, s0, 2);
        s1 += __shfl_xor_sync(0xffffffffu, s1, 1); s1 += __shfl_xor_sync(0xffffffffu, s1, 2);
        const float i0 = 1.f / s0, i1 = 1.f / s1;

        float o[4][4];
#pragma unroll
        for (int nf = 0; nf < 4; nf++)
#pragma unroll
            for (int e = 0; e < 4; e++) o[nf][e] = 0.f;
#pragma unroll
        for (int j = 0; j < 4; j++) {
            const uint32_t a0 = h2pack(lo[2 * j][0], lo[2 * j][1]);
            const uint32_t a1 = h2pack(hi[2 * j][0], hi[2 * j][1]);
            const uint32_t a2 = (j < 3) ? h2pack(lo[2 * j + 1][0], lo[2 * j + 1][1]) : 0u;
            const uint32_t a3 = (j < 3) ? h2pack(hi[2 * j + 1][0], hi[2 * j + 1][1]) : 0u;
#pragma unroll
            for (int nf = 0; nf < 4; nf++) {
                uint2 vv = vp2[((h * 4 + nf) * 4 + j) * 32 + lane];
                mma16h(o[nf], a0, a1, a2, a3, vv.x, vv.y);
            }
        }
        uint32_t* ao2 = (uint32_t*)g_ao;
#pragma unroll
        for (int nf = 0; nf < 4; nf++) {
            const int col = h * 32 + nf * 8 + 2 * tig;
            if (v0) ao2[((row0 + r0) * DIM + col) >> 1] =
                h2pack(o[nf][0] * i0, o[nf][1] * i0);
            if (v1) ao2[((row0 + r1) * DIM + col) >> 1] =
                h2pack(o[nf][2] * i1, o[nf][3] * i1);
        }
    }
}

extern "C" void kernel_launch(void* const* d_in, const int* in_sizes, int n_in,
                              void* d_out, int out_size)
{
    const float* x      = (const float*)d_in[0];
    const float* mask   = (const float*)d_in[1];
    const float* w_qkv  = (const float*)d_in[2];
    const float* b_qkv  = (const float*)d_in[3];
    const float* btab   = (const float*)d_in[4];
    const float* w_proj = (const float*)d_in[5];
    const float* b_proj = (const float*)d_in[6];
    const int*   relidx = (const int*)  d_in[7];
    float* out = (float*)d_out;

    cudaFuncSetAttribute(gemm_k128<0>, cudaFuncAttributeMaxDynamicSharedMemorySize,
                         GEMM_SMEMF * 4);
    cudaFuncSetAttribute(gemm_k128<1>, cudaFuncAttributeMaxDynamicSharedMemorySize,
                         GEMM_SMEMF * 4);
    cudaFuncSetAttribute(attn_kernel, cudaFuncAttributeMaxDynamicSharedMemorySize,
                         ATTN_SMEMB);

    prep_kernel<<<16, 512>>>(w_qkv, w_proj);
    prep_bm<<<1274, 512>>>(mask, btab, relidx);
    gemm_k128<0><<<3136, 256, GEMM_SMEMF * 4>>>(x, b_qkv, nullptr);
    attn_kernel<<<NWIN, 256, ATTN_SMEMB>>>(0);
    gemm_k128<1><<<3136, 256, GEMM_SMEMF * 4>>>(nullptr, b_proj, out);
}

// round 17
// speedup vs baseline: 1.5360x; 1.0325x over previous
#include <cuda_runtime.h>
#include <cuda_fp16.h>
#include <cstdint>

#define NTOK   49
#define DIM    128
#define NWIN   4096
#define SCALE  0.17677669529663687f

// ---- global scratch (static __device__, no allocation) ----
__device__ __align__(16) float g_wq[49152];        // w_qkv fp16 B-frags (6144 uint4)
__device__ __align__(16) float g_wp[16384];        // w_proj fp16 B-frags (2048 uint4)
__device__ __align__(16) __half g_qkv[77070336];   // [200704][384] fp16 Q(scaled)|K|V
__device__ __align__(16) __half g_ao[25690112];    // [200704][128] fp16 attention output
__device__ __align__(16) uint16_t g_bm[652288];    // [64][4][49][52] bf16 bias+mask

__device__ __forceinline__ void mma16h(float* c, uint32_t a0, uint32_t a1,
                                       uint32_t a2, uint32_t a3,
                                       uint32_t b0, uint32_t b1) {
    asm("mma.sync.aligned.m16n8k16.row.col.f32.f16.f16.f32 "
        "{%0,%1,%2,%3},{%4,%5,%6,%7},{%8,%9},{%0,%1,%2,%3};"
        : "+f"(c[0]), "+f"(c[1]), "+f"(c[2]), "+f"(c[3])
        : "r"(a0), "r"(a1), "r"(a2), "r"(a3), "r"(b0), "r"(b1));
}
__device__ __forceinline__ uint32_t h2pack(float lo, float hi) {
    __half2 h = __floats2half2_rn(lo, hi);
    return *reinterpret_cast<uint32_t*>(&h);
}
__device__ __forceinline__ void cpa16(uint32_t s, const void* g) {
    asm volatile("cp.async.cg.shared.global [%0], [%1], 16;" :: "r"(s), "l"(g));
}
__device__ __forceinline__ uint32_t smem_u32(const void* p) {
    uint32_t a;
    asm("{ .reg .u64 t; cvta.to.shared.u64 t, %1; cvt.u32.u64 %0, t; }" : "=r"(a) : "l"(p));
    return a;
}
__device__ __forceinline__ uint16_t f2bf(float f) {
    uint32_t u = __float_as_uint(f);
    return (uint16_t)((u + 0x7fffu + ((u >> 16) & 1u)) >> 16);
}

// ---- prep: pack weights into fp16 B-frag uint4s ----
__global__ void prep_kernel(const float* __restrict__ wq, const float* __restrict__ wp) {
    int o = blockIdx.x * blockDim.x + threadIdx.x;        // 8192 uint4
    const float* W;
    int ncols, nbase, rem;
    if (o < 6144) { W = wq; ncols = 384; nbase = (o >> 11) * 128; rem = o & 2047; }
    else          { W = wp; ncols = 128; nbase = 0;               rem = o - 6144; }
    const int nt = rem >> 8, kt = (rem >> 5) & 7, l = rem & 31;
    const int gd = l >> 2, tg = l & 3;
    const int n = nbase + nt * 16 + gd;
    const int k0 = kt * 16 + 2 * tg;
    uint4 v;
    v.x = h2pack(W[k0 * ncols + n],           W[(k0 + 1) * ncols + n]);
    v.y = h2pack(W[(k0 + 8) * ncols + n],     W[(k0 + 9) * ncols + n]);
    v.z = h2pack(W[k0 * ncols + n + 8],       W[(k0 + 1) * ncols + n + 8]);
    v.w = h2pack(W[(k0 + 8) * ncols + n + 8], W[(k0 + 9) * ncols + n + 8]);
    if (o < 6144) ((uint4*)g_wq)[o] = v;
    else          ((uint4*)g_wp)[o - 6144] = v;
}

// ---- prep_bm: bm[w][h][r][c52] = btab[ri[r,c],h] + mask[w,r,c]  (bf16) ----
__global__ void prep_bm(const float* __restrict__ mask, const float* __restrict__ btab,
                        const int* __restrict__ relidx) {
    int o = blockIdx.x * blockDim.x + threadIdx.x;        // 652288 total
    if (o >= 652288) return;
    int c = o % 52;
    int t = o / 52;
    int r = t % 49; t /= 49;
    int h = t & 3;
    int w = t >> 2;
    float v = 0.f;
    if (c < 49)
        v = btab[relidx[r * 49 + c] * 4 + h] + mask[w * 2401 + r * 49 + c];
    g_bm[o] = f2bf(v);
}

// ============================================================
// GEMM (fp16 mma): C[64 x NO] = A * B + bias, K=128, NS slices
// ============================================================
#define GA_LD 132
#define GS_B  8448
#define GS_BS 16640
#define GEMM_SMEMF 17024

template<int MODE>
__global__ void __launch_bounds__(256, 3)
gemm_k128(const float* __restrict__ Aext, const float* __restrict__ bias,
          float* __restrict__ Cext)
{
    extern __shared__ float sm[];
    float* bs = sm + GS_BS;
    const int tid = threadIdx.x, wid = tid >> 5, lane = tid & 31;
    const int gid = lane >> 2, tig = lane & 3;
    const uint32_t su = smem_u32(sm);

    const float* Bp = (MODE == 0) ? g_wq : g_wp;
    const int    NO = (MODE == 0) ? 384 : 128;
    const int    NS = (MODE == 0) ? 3 : 1;

    const size_t arow0 = (size_t)blockIdx.x * 64;
    if (MODE == 0) {
        for (int i = tid; i < 2048; i += 256) {           // raw A fp32 64x128
            int r = i >> 5, c4 = i & 31;
            cpa16(su + (r * GA_LD + c4 * 4) * 4, Aext + (arow0 + r) * DIM + c4 * 4);
        }
    } else {
        for (int i = tid; i < 1024; i += 256) {           // raw A fp16 64x128, stride 136 halves
            int r = i >> 4, c8 = i & 15;
            cpa16(su + r * 272 + c8 * 16, g_ao + (arow0 + r) * DIM + c8 * 8);
        }
    }
    for (int i = tid; i < NO / 4; i += 256)               // bias
        cpa16(su + (GS_BS + i * 4) * 4, bias + i * 4);
    asm volatile("cp.async.commit_group;");
    for (int i = tid; i < 2048; i += 256)                 // B slice 0 (8192 words)
        cpa16(su + (GS_B + i * 4) * 4, Bp + i * 4);
    asm volatile("cp.async.commit_group;");
    asm volatile("cp.async.wait_group 1;");
    __syncthreads();

    // ---- one-time in-smem A repack to fp16 A-frags (1024 uint4) ----
    uint4 stg[4];
#pragma unroll
    for (int j = 0; j < 4; j++) {
        const int u = tid + 256 * j;
        const int mt = u >> 8, kt = (u >> 5) & 7;
        const int l = u & 31, gd = l >> 2, tg = l & 3;
        const int r = mt * 16 + gd;
        const int k0 = kt * 16 + 2 * tg;
        if (MODE == 0) {
            stg[j].x = h2pack(sm[r * GA_LD + k0],           sm[r * GA_LD + k0 + 1]);
            stg[j].y = h2pack(sm[(r + 8) * GA_LD + k0],     sm[(r + 8) * GA_LD + k0 + 1]);
            stg[j].z = h2pack(sm[r * GA_LD + k0 + 8],       sm[r * GA_LD + k0 + 9]);
            stg[j].w = h2pack(sm[(r + 8) * GA_LD + k0 + 8], sm[(r + 8) * GA_LD + k0 + 9]);
        } else {
            const uint32_t* Sw = (const uint32_t*)sm;
            stg[j].x = Sw[r * 68 + kt * 8 + tg];
            stg[j].y = Sw[(r + 8) * 68 + kt * 8 + tg];
            stg[j].z = Sw[r * 68 + kt * 8 + tg + 4];
            stg[j].w = Sw[(r + 8) * 68 + kt * 8 + tg + 4];
        }
    }
    __syncthreads();
    {
        uint4* Aw4 = (uint4*)sm;
#pragma unroll
        for (int j = 0; j < 4; j++) Aw4[tid + 256 * j] = stg[j];
    }
    asm volatile("cp.async.wait_group 0;");
    __syncthreads();

    const int mw = wid & 1, nw = wid >> 1;
    const uint4* Ap4 = (const uint4*)sm;
    const uint4* Bp4 = (const uint4*)(sm + GS_B);

#pragma unroll 1
    for (int t = 0; t < NS; t++) {
        float c[2][4][4];
#pragma unroll
        for (int f = 0; f < 2; f++)
#pragma unroll
            for (int j = 0; j < 4; j++)
#pragma unroll
                for (int e = 0; e < 4; e++) c[f][j][e] = 0.f;

#pragma unroll
        for (int kt = 0; kt < 8; kt++) {
            uint4 av0 = Ap4[((mw * 2 + 0) * 8 + kt) * 32 + lane];
            uint4 av1 = Ap4[((mw * 2 + 1) * 8 + kt) * 32 + lane];
            uint4 bv0 = Bp4[((nw * 2 + 0) * 8 + kt) * 32 + lane];
            uint4 bv1 = Bp4[((nw * 2 + 1) * 8 + kt) * 32 + lane];
            mma16h(c[0][0], av0.x, av0.y, av0.z, av0.w, bv0.x, bv0.y);
            mma16h(c[0][1], av0.x, av0.y, av0.z, av0.w, bv0.z, bv0.w);
            mma16h(c[0][2], av0.x, av0.y, av0.z, av0.w, bv1.x, bv1.y);
            mma16h(c[0][3], av0.x, av0.y, av0.z, av0.w, bv1.z, bv1.w);
            mma16h(c[1][0], av1.x, av1.y, av1.z, av1.w, bv0.x, bv0.y);
            mma16h(c[1][1], av1.x, av1.y, av1.z, av1.w, bv0.z, bv0.w);
            mma16h(c[1][2], av1.x, av1.y, av1.z, av1.w, bv1.x, bv1.y);
            mma16h(c[1][3], av1.x, av1.y, av1.z, av1.w, bv1.z, bv1.w);
        }

        __syncthreads();
        if (t + 1 < NS) {
            const float* Bn = Bp + (t + 1) * 8192;
            for (int i = tid; i < 2048; i += 256)
                cpa16(su + (GS_B + i * 4) * 4, Bn + i * 4);
            asm volatile("cp.async.commit_group;");
        }

        const int   cb = t * 128;
        const float sc = (MODE == 0 && t == 0) ? SCALE : 1.f;
#pragma unroll
        for (int f = 0; f < 2; f++) {
            const size_t r0 = arow0 + (mw * 2 + f) * 16 + gid;
#pragma unroll
            for (int j = 0; j < 4; j++) {
                const int cl = nw * 32 + j * 8 + 2 * tig;
                const float b0 = bs[cb + cl], b1 = bs[cb + cl + 1];
                const int cg = cb + cl;
                if (MODE == 0) {
                    uint32_t* C2 = (uint32_t*)g_qkv;
                    C2[(r0 * 384 + cg) >> 1] =
                        h2pack((c[f][j][0] + b0) * sc, (c[f][j][1] + b1) * sc);
                    C2[((r0 + 8) * 384 + cg) >> 1] =
                        h2pack((c[f][j][2] + b0) * sc, (c[f][j][3] + b1) * sc);
                } else {
                    *(float2*)&Cext[r0 * 128 + cg] =
                        make_float2(c[f][j][0] + b0, c[f][j][1] + b1);
                    *(float2*)&Cext[(r0 + 8) * 128 + cg] =
                        make_float2(c[f][j][2] + b0, c[f][j][3] + b1);
                }
            }
        }
        if (t + 1 < NS) {
            asm volatile("cp.async.wait_group 0;");
            __syncthreads();
        }
    }
}

// ============================================================
// Attention, 3 CTAs/SM: Q|K staged 56x264 halves; V staged raw in
// frag region and repacked in place (register-staged); bf16 bias+mask.
// smem: QK 29568 | VP 16384 | BM 20384 = 66336 B
// ============================================================
#define AS_VP_B 29568
#define AS_BM_B 45952
#define ATTN_SMEMB 66336

__global__ void __launch_bounds__(256, 3)
attn_kernel(int dummy)
{
    extern __shared__ float sm[];
    const uint32_t* stw = (const uint32_t*)sm;            // QK staging as words (stride 132)
    const uint32_t* bm32 = (const uint32_t*)((const char*)sm + AS_BM_B);
    const int tid = threadIdx.x, wid = tid >> 5, lane = tid & 31;
    const int gid = lane >> 2, tig = lane & 3;
    const uint32_t su = smem_u32(sm);

    const int wb = blockIdx.x;
    const size_t row0 = (size_t)wb * NTOK;
    for (int i = tid; i < 1568; i += 256) {               // Q|K fp16 49x256, stride 264 halves
        int r = i >> 5, c = i & 31;
        cpa16(su + r * 528 + c * 16, g_qkv + (row0 + r) * 384 + c * 8);
    }
    for (int i = tid; i < 784; i += 256) {                // V raw fp16 49x128 -> VP region
        int r = i >> 4, c = i & 15;
        cpa16(su + AS_VP_B + r * 256 + c * 16, g_qkv + (row0 + r) * 384 + 256 + c * 8);
    }
    const int w = wb & 63;
    {
        const char* bsrc = (const char*)g_bm + (size_t)w * 20384;
        for (int i = tid; i < 1274; i += 256)
            cpa16(su + AS_BM_B + i * 16, bsrc + i * 16);
    }
    {                                                      // zero QK rows 49..55
        uint32_t* zw = (uint32_t*)sm;
        for (int i = tid; i < 924; i += 256) zw[6468 + i] = 0;
    }
    asm volatile("cp.async.commit_group;\n\tcp.async.wait_group 0;");
    __syncthreads();

    // ---- V repack IN PLACE (register-staged: gather all, sync, scatter) ----
    {
        const unsigned short* vsts = (const unsigned short*)((const char*)sm + AS_VP_B);
        uint2 stg[8];
#pragma unroll
        for (int j = 0; j < 8; j++) {
            const int u = tid + 256 * j;
            const int l = u & 31, idx = u >> 5;
            const int j4 = idx & 3, nf = (idx >> 2) & 3, hh = idx >> 4;
            const int gd = l >> 2, tg = l & 3;
            const int col = hh * 32 + nf * 8 + gd;
            const int ra = 16 * j4 + 2 * tg;
            uint32_t fa = (ra     < NTOK) ? vsts[ ra      * 128 + col] : 0u;
            uint32_t fb = (ra + 1 < NTOK) ? vsts[(ra + 1) * 128 + col] : 0u;
            uint32_t fc = (ra + 8 < NTOK) ? vsts[(ra + 8) * 128 + col] : 0u;
            uint32_t fd = (ra + 9 < NTOK) ? vsts[(ra + 9) * 128 + col] : 0u;
            stg[j].x = fa | (fb << 16);
            stg[j].y = fc | (fd << 16);
        }
        __syncthreads();
        uint2* vp2w = (uint2*)((char*)sm + AS_VP_B);
#pragma unroll
        for (int j = 0; j < 8; j++) vp2w[tid + 256 * j] = stg[j];
    }
    __syncthreads();

    const uint2* vp2 = (const uint2*)((const char*)sm + AS_VP_B);
    const int h = wid & 3, mt = wid >> 2;
#pragma unroll 1
    for (int sub = 0; sub < 2; sub++) {
        const int m0 = (mt * 2 + sub) * 16;
        const bool hiO = (m0 == 48);

        uint32_t aq[2][4];
#pragma unroll
        for (int kt = 0; kt < 2; kt++) {
            const int base = (m0 + gid) * 132 + h * 16 + kt * 8 + tig;
            aq[kt][0] = stw[base];
            aq[kt][2] = stw[base + 4];
            aq[kt][1] = hiO ? 0u : stw[base + 8 * 132];
            aq[kt][3] = hiO ? 0u : stw[base + 8 * 132 + 4];
        }
        float s_[7][4];
#pragma unroll
        for (int nt = 0; nt < 7; nt++) {
            float cc[4] = {0.f, 0.f, 0.f, 0.f};
#pragma unroll
            for (int kt = 0; kt < 2; kt++) {
                const int kb = (nt * 8 + gid) * 132 + 64 + h * 16 + kt * 8 + tig;
                mma16h(cc, aq[kt][0], aq[kt][1], aq[kt][2], aq[kt][3],
                       stw[kb], stw[kb + 4]);
            }
#pragma unroll
            for (int e = 0; e < 4; e++) s_[nt][e] = cc[e];
        }

        const int r0 = m0 + gid, r1 = r0 + 8;
        const bool v0 = r0 < NTOK, v1 = r1 < NTOK;
        const int br0 = (h * 49 + (v0 ? r0 : 0)) * 26;
        const int br1 = (h * 49 + (v1 ? r1 : 0)) * 26;
        float lo[7][2], hi[7][2];
        float mx0 = -1e30f, mx1 = -1e30f;
#pragma unroll
        for (int nt = 0; nt < 7; nt++) {
            const int cc0 = nt * 8 + 2 * tig;
            const uint32_t bv0 = bm32[br0 + nt * 4 + tig];
            const uint32_t bv1 = bm32[br1 + nt * 4 + tig];
            const float b00 = __uint_as_float(bv0 << 16);
            const float b01 = __uint_as_float(bv0 & 0xffff0000u);
            const float b10 = __uint_as_float(bv1 << 16);
            const float b11 = __uint_as_float(bv1 & 0xffff0000u);
            lo[nt][0] = (v0 && cc0     < NTOK) ? s_[nt][0] + b00 : -1e30f;
            lo[nt][1] = (v0 && cc0 + 1 < NTOK) ? s_[nt][1] + b01 : -1e30f;
            hi[nt][0] = (v1 && cc0     < NTOK) ? s_[nt][2] + b10 : -1e30f;
            hi[nt][1] = (v1 && cc0 + 1 < NTOK) ? s_[nt][3] + b11 : -1e30f;
            mx0 = fmaxf(mx0, fmaxf(lo[nt][0], lo[nt][1]));
            mx1 = fmaxf(mx1, fmaxf(hi[nt][0], hi[nt][1]));
        }
        mx0 = fmaxf(mx0, __shfl_xor_sync(0xffffffffu, mx0, 1));
        mx0 = fmaxf(mx0, __shfl_xor_sync(0xffffffffu, mx0, 2));
        mx1 = fmaxf(mx1, __shfl_xor_sync(0xffffffffu, mx1, 1));
        mx1 = fmaxf(mx1, __shfl_xor_sync(0xffffffffu, mx1, 2));
        float s0 = 0.f, s1 = 0.f;
#pragma unroll
        for (int nt = 0; nt < 7; nt++)
#pragma unroll
            for (int s = 0; s < 2; s++) {
                float e0 = __expf(lo[nt][s] - mx0);
                float e1 = __expf(hi[nt][s] - mx1);
                lo[nt][s] = e0; hi[nt][s] = e1;
                s0 += e0; s1 += e1;
            }
        s0 += __shfl_xor_sync(0xffffffffu, s0, 1); s0 += __shfl_xor_sync(0xffffffffu, s0, 2);
        s1 += __shfl_xor_sync(0xffffffffu, s1, 1); s1 += __shfl_xor_sync(0xffffffffu, s1, 2);
        const float i0 = 1.f / s0, i1 = 1.f / s1;

        float o[4][4];
#pragma unroll
        for (int nf = 0; nf < 4; nf++)
#pragma unroll
            for (int e = 0; e < 4; e++) o[nf][e] = 0.f;
#pragma unroll
        for (int j = 0; j < 4; j++) {
            const uint32_t a0 = h2pack(lo[2 * j][0], lo[2 * j][1]);
            const uint32_t a1 = h2pack(hi[2 * j][0], hi[2 * j][1]);
            const uint32_t a2 = (j < 3) ? h2pack(lo[2 * j + 1][0], lo[2 * j + 1][1]) : 0u;
            const uint32_t a3 = (j < 3) ? h2pack(hi[2 * j + 1][0], hi[2 * j + 1][1]) : 0u;
#pragma unroll
            for (int nf = 0; nf < 4; nf++) {
                uint2 vv = vp2[((h * 4 + nf) * 4 + j) * 32 + lane];
                mma16h(o[nf], a0, a1, a2, a3, vv.x, vv.y);
            }
        }
        uint32_t* ao2 = (uint32_t*)g_ao;
#pragma unroll
        for (int nf = 0; nf < 4; nf++) {
            const int col = h * 32 + nf * 8 + 2 * tig;
            if (v0) ao2[((row0 + r0) * DIM + col) >> 1] =
                h2pack(o[nf][0] * i0, o[nf][1] * i0);
            if (v1) ao2[((row0 + r1) * DIM + col) >> 1] =
                h2pack(o[nf][2] * i1, o[nf][3] * i1);
        }
    }
}

extern "C" void kernel_launch(void* const* d_in, const int* in_sizes, int n_in,
                              void* d_out, int out_size)
{
    const float* x      = (const float*)d_in[0];
    const float* mask   = (const float*)d_in[1];
    const float* w_qkv  = (const float*)d_in[2];
    const float* b_qkv  = (const float*)d_in[3];
    const float* btab   = (const float*)d_in[4];
    const float* w_proj = (const float*)d_in[5];
    const float* b_proj = (const float*)d_in[6];
    const int*   relidx = (const int*)  d_in[7];
    float* out = (float*)d_out;

    cudaFuncSetAttribute(gemm_k128<0>, cudaFuncAttributeMaxDynamicSharedMemorySize,
                         GEMM_SMEMF * 4);
    cudaFuncSetAttribute(gemm_k128<1>, cudaFuncAttributeMaxDynamicSharedMemorySize,
                         GEMM_SMEMF * 4);
    cudaFuncSetAttribute(attn_kernel, cudaFuncAttributeMaxDynamicSharedMemorySize,
                         ATTN_SMEMB);

    prep_kernel<<<16, 512>>>(w_qkv, w_proj);
    prep_bm<<<1274, 512>>>(mask, btab, relidx);
    gemm_k128<0><<<3136, 256, GEMM_SMEMF * 4>>>(x, b_qkv, nullptr);
    attn_kernel<<<NWIN, 256, ATTN_SMEMB>>>(0);
    gemm_k128<1><<<3136, 256, GEMM_SMEMF * 4>>>(nullptr, b_proj, out);
}